// round 12
// baseline (speedup 1.0000x reference)
#include <cuda_runtime.h>
#include <cuda_bf16.h>
#include <cstdint>

// ---------------- problem constants ----------------
#define BB 2
#define SS 2048
#define DD 2048
#define HH 16
#define NOPE 128
#define ROPE 64
#define VDIM 128
#define QKD 192           // NOPE + ROPE
#define KV_RANK 512
#define KV_A (KV_RANK + ROPE)   // 576
#define KV_PROJ (HH * (NOPE + VDIM)) // 4096
#define EPSV 1e-6f
#define ATT_SCALE 0.07216878364870323f  // 192^-0.5

// ---------------- fp32 scratch ----------------
__device__ __align__(16) float g_qraw  [(size_t)BB * SS * HH * QKD];
__device__ __align__(16) float g_kvall [(size_t)BB * SS * KV_A];
__device__ __align__(16) float g_kvproj[(size_t)BB * SS * KV_PROJ];

// ---------------- bf16 hi/lo scratch ----------------
__device__ __align__(16) __nv_bfloat16 g_xh   [(size_t)BB * SS * DD];
__device__ __align__(16) __nv_bfloat16 g_xl   [(size_t)BB * SS * DD];
__device__ __align__(16) __nv_bfloat16 g_wqh  [(size_t)(HH * QKD) * DD];
__device__ __align__(16) __nv_bfloat16 g_wql  [(size_t)(HH * QKD) * DD];
__device__ __align__(16) __nv_bfloat16 g_wkvah[(size_t)KV_A * DD];
__device__ __align__(16) __nv_bfloat16 g_wkval[(size_t)KV_A * DD];
__device__ __align__(16) __nv_bfloat16 g_wkvbh[(size_t)KV_PROJ * KV_RANK];
__device__ __align__(16) __nv_bfloat16 g_wkvbl[(size_t)KV_PROJ * KV_RANK];
__device__ __align__(16) __nv_bfloat16 g_woh  [(size_t)DD * DD];
__device__ __align__(16) __nv_bfloat16 g_wol  [(size_t)DD * DD];
__device__ __align__(16) __nv_bfloat16 g_kvnh [(size_t)BB * SS * KV_RANK];
__device__ __align__(16) __nv_bfloat16 g_kvnl [(size_t)BB * SS * KV_RANK];
__device__ __align__(16) __nv_bfloat16 g_Qh   [(size_t)BB * HH * SS * QKD];
__device__ __align__(16) __nv_bfloat16 g_Ql   [(size_t)BB * HH * SS * QKD];
__device__ __align__(16) __nv_bfloat16 g_Kh   [(size_t)BB * HH * SS * QKD];
__device__ __align__(16) __nv_bfloat16 g_Kl   [(size_t)BB * HH * SS * QKD];
__device__ __align__(16) __nv_bfloat16 g_Vth  [(size_t)BB * HH * VDIM * SS];
__device__ __align__(16) __nv_bfloat16 g_Vtl  [(size_t)BB * HH * VDIM * SS];
__device__ __align__(16) __nv_bfloat16 g_a2h  [(size_t)BB * SS * HH * VDIM];
__device__ __align__(16) __nv_bfloat16 g_a2l  [(size_t)BB * SS * HH * VDIM];

// ---------------- helpers ----------------
__device__ __forceinline__ uint32_t smem_u32(const void* p) {
    uint32_t a;
    asm("{ .reg .u64 t; cvta.to.shared.u64 t, %1; cvt.u32.u64 %0, t; }" : "=r"(a) : "l"(p));
    return a;
}
__device__ __forceinline__ void split2(float x, __nv_bfloat16& h, __nv_bfloat16& l) {
    h = __float2bfloat16_rn(x);
    l = __float2bfloat16_rn(x - __bfloat162float(h));
}
__device__ __forceinline__ void packP(float a, float b, unsigned& hi, unsigned& lo) {
    __nv_bfloat16 ha = __float2bfloat16_rn(a);
    __nv_bfloat16 hb = __float2bfloat16_rn(b);
    __nv_bfloat16 la = __float2bfloat16_rn(a - __bfloat162float(ha));
    __nv_bfloat16 lb = __float2bfloat16_rn(b - __bfloat162float(hb));
    hi = ((unsigned)__bfloat16_as_ushort(hb) << 16) | __bfloat16_as_ushort(ha);
    lo = ((unsigned)__bfloat16_as_ushort(lb) << 16) | __bfloat16_as_ushort(la);
}
__device__ __forceinline__ void cp16(uint32_t d, const void* s) {
    asm volatile("cp.async.cg.shared.global [%0], [%1], 16;" :: "r"(d), "l"(s));
}
__device__ __forceinline__ void cp16z(uint32_t d, const void* s, unsigned bytes) {
    asm volatile("cp.async.cg.shared.global [%0], [%1], 16, %2;" :: "r"(d), "l"(s), "r"(bytes));
}

#define MMA16816(d, a, b) \
    asm volatile("mma.sync.aligned.m16n8k16.row.col.f32.bf16.bf16.f32 " \
                 "{%0,%1,%2,%3}, {%4,%5,%6,%7}, {%8,%9}, {%0,%1,%2,%3};" \
                 : "+f"((d)[0]), "+f"((d)[1]), "+f"((d)[2]), "+f"((d)[3]) \
                 : "r"((a)[0]), "r"((a)[1]), "r"((a)[2]), "r"((a)[3]), \
                   "r"((b)[0]), "r"((b)[1]))

#define LDMX4(r, ad) \
    asm volatile("ldmatrix.sync.aligned.m8n8.x4.shared.b16 {%0,%1,%2,%3}, [%4];" \
                 : "=r"((r)[0]), "=r"((r)[1]), "=r"((r)[2]), "=r"((r)[3]) : "r"(ad))
#define LDMX2(r, ad) \
    asm volatile("ldmatrix.sync.aligned.m8n8.x2.shared.b16 {%0,%1}, [%2];" \
                 : "=r"((r)[0]), "=r"((r)[1]) : "r"(ad))

// ======== bf16x3 GEMM: CTA 128x128, warp 64x32, 3-stage cp.async (R8) =========
#define MOFF 8192u
#define STG  32768u
#define GEMM3_SMEM 98304

__device__ __forceinline__ void g3_issue(
    uint32_t sb,
    const __nv_bfloat16* __restrict__ Ah, const __nv_bfloat16* __restrict__ Al,
    const __nv_bfloat16* __restrict__ Bh, const __nv_bfloat16* __restrict__ Bl,
    int bm, int bn, int N, int lda, int ldb, int k0, int tid)
{
#pragma unroll
    for (int half = 0; half < 2; half++) {
        int r  = (tid >> 2) + half * 64;
        int sg = tid & 3;
        int p  = sg ^ ((r >> 1) & 3);
        uint32_t d = sb + (uint32_t)(r * 64 + p * 16);
        long long ko = (long long)k0 + sg * 8;
        cp16(d,        Ah + (long long)(bm + r) * lda + ko);
        cp16(d + MOFF, Al + (long long)(bm + r) * lda + ko);
        int gn = bn + r;
        unsigned bytes = (gn < N) ? 16u : 0u;
        int gr = (gn < N) ? gn : 0;
        cp16z(d + 2 * MOFF, Bh + (long long)gr * ldb + ko, bytes);
        cp16z(d + 3 * MOFF, Bl + (long long)gr * ldb + ko, bytes);
    }
    asm volatile("cp.async.commit_group;" ::: "memory");
}

__global__ __launch_bounds__(256, 2) void gemm3(
    const __nv_bfloat16* __restrict__ Ah, const __nv_bfloat16* __restrict__ Al,
    const __nv_bfloat16* __restrict__ Bh, const __nv_bfloat16* __restrict__ Bl,
    float* __restrict__ C,
    int M, int N, int K, int lda, int ldb, int ldc,
    long long sA, long long sB, long long sC, float alpha)
{
    extern __shared__ char sm[];
    const int z = blockIdx.z;
    Ah += z * sA; Al += z * sA; Bh += z * sB; Bl += z * sB; C += z * sC;

    const int tid  = threadIdx.x;
    const int lane = tid & 31;
    const int wid  = tid >> 5;
    const int g    = lane >> 2;
    const int tig  = lane & 3;
    const int wm   = wid >> 2;
    const int wn   = wid & 3;
    const int bm = blockIdx.y * 128;
    const int bn = blockIdx.x * 128;
    const uint32_t smb = smem_u32(sm);

    float acc[4][4][4];
#pragma unroll
    for (int i = 0; i < 4; i++)
#pragma unroll
        for (int j = 0; j < 4; j++)
#pragma unroll
            for (int q = 0; q < 4; q++) acc[i][j][q] = 0.f;

    const int nc = K >> 5;

    g3_issue(smb,       Ah, Al, Bh, Bl, bm, bn, N, lda, ldb, 0,  tid);
    g3_issue(smb + STG, Ah, Al, Bh, Bl, bm, bn, N, lda, ldb, 32, tid);

    const int l15 = lane & 15;
    const int l7  = lane & 7;
    const uint32_t aSel = (uint32_t)(lane >> 4);
    const uint32_t bSel = (uint32_t)(l15 >> 3);
    const uint32_t swzA = (uint32_t)((l15 >> 1) & 3);
    const uint32_t swzB = (uint32_t)((l7 >> 1) & 3);
    const uint32_t aBase = smb + (uint32_t)((wm * 64 + l15) * 64);
    const uint32_t bBase = smb + 2u * MOFF + (uint32_t)((wn * 32 + l7) * 64);

    for (int c = 0; c < nc; c++) {
        asm volatile("cp.async.wait_group 1;" ::: "memory");
        __syncthreads();

        if (c + 2 < nc) {
            g3_issue(smb + (uint32_t)((c + 2) % 3) * STG,
                     Ah, Al, Bh, Bl, bm, bn, N, lda, ldb, (c + 2) << 5, tid);
        } else {
            asm volatile("cp.async.commit_group;" ::: "memory");
        }

        const uint32_t so = (uint32_t)(c % 3) * STG;
#pragma unroll
        for (int kk = 0; kk < 2; kk++) {
            const uint32_t cA = (uint32_t)(kk * 2) + aSel;
            const uint32_t cB = (uint32_t)(kk * 2) + bSel;
            unsigned bh[4][2], blr[4][2];
#pragma unroll
            for (int nf = 0; nf < 4; nf++) {
                uint32_t ad = bBase + so + (uint32_t)(nf * 512) + ((cB ^ swzB) << 4);
                LDMX2(bh[nf], ad);
                LDMX2(blr[nf], ad + MOFF);
            }
#pragma unroll
            for (int mf = 0; mf < 4; mf++) {
                uint32_t ad = aBase + so + (uint32_t)(mf * 1024) + ((cA ^ swzA) << 4);
                unsigned ah[4], al[4];
                LDMX4(ah, ad);
                LDMX4(al, ad + MOFF);
#pragma unroll
                for (int nf = 0; nf < 4; nf++) {
                    MMA16816(acc[mf][nf], ah, bh[nf]);
                    MMA16816(acc[mf][nf], ah, blr[nf]);
                    MMA16816(acc[mf][nf], al, bh[nf]);
                }
            }
        }
    }

#pragma unroll
    for (int mf = 0; mf < 4; mf++) {
#pragma unroll
        for (int nf = 0; nf < 4; nf++) {
            int row = bm + wm * 64 + mf * 16 + g;
            int col = bn + wn * 32 + nf * 8 + 2 * tig;
            if (col < N) {
                float* p0 = C + (long long)row * ldc + col;
                p0[0] = alpha * acc[mf][nf][0];
                p0[1] = alpha * acc[mf][nf][1];
                float* p1 = p0 + (long long)8 * ldc;
                p1[0] = alpha * acc[mf][nf][2];
                p1[1] = alpha * acc[mf][nf][3];
            }
        }
    }
}

// ================= fused flash attention (bf16x3, online softmax) =============
// Grid (16 q-tiles, 32 bh). 256 thr, 8 warps = 4 qm x 2 kvw.
// Warp tile: 32 q-rows x 64 kv-cols (square -> minimal smem bytes per MMA).
// kv halves run independent online softmax; merged once at the end via smem.
// SMEM: Q 6 ch x (hi 8K | lo 8K at +49152) = 98304
//       K 3 stages x (hi 8K + lo 8K) at 98304
//       V 4 ch x (hi 8K + lo 8K) at 147456.   Total 212992.
#define FA_KOFF 98304u
#define FA_QLO  49152u
#define FA_VOFF 147456u
#define FA_SMEM 212992

__device__ __forceinline__ void fa_issueK(
    uint32_t smb, int stage,
    const __nv_bfloat16* __restrict__ Khp, const __nv_bfloat16* __restrict__ Klp,
    int c, int tid)
{
#pragma unroll
    for (int it = 0; it < 2; it++) {
        int u = tid + (it << 8);
        int r = u >> 2, sg = u & 3;
        int p = sg ^ ((r >> 1) & 3);
        uint32_t d = smb + FA_KOFF + (uint32_t)(stage * 16384 + r * 64 + p * 16);
        long long off = (long long)r * QKD + c * 32 + sg * 8;
        cp16(d,         Khp + off);
        cp16(d + 8192u, Klp + off);
    }
    asm volatile("cp.async.commit_group;" ::: "memory");
}

__device__ __forceinline__ void fa_issueV(
    uint32_t smb,
    const __nv_bfloat16* __restrict__ Vhp, const __nv_bfloat16* __restrict__ Vlp,
    int j, int tid)
{
#pragma unroll
    for (int it = 0; it < 8; it++) {
        int u = tid + (it << 8);            // 0..2047
        int cb = u >> 9, v = u & 511;
        int r = v >> 2, sg = v & 3;
        int p = sg ^ ((r >> 1) & 3);
        uint32_t d = smb + FA_VOFF + (uint32_t)(cb * 16384 + r * 64 + p * 16);
        long long off = (long long)r * SS + j * 128 + cb * 32 + sg * 8;
        cp16(d,         Vhp + off);
        cp16(d + 8192u, Vlp + off);
    }
    asm volatile("cp.async.commit_group;" ::: "memory");
}

__global__ __launch_bounds__(256, 1) void fa_kernel(
    const __nv_bfloat16* __restrict__ Qh, const __nv_bfloat16* __restrict__ Ql,
    const __nv_bfloat16* __restrict__ Kh, const __nv_bfloat16* __restrict__ Kl,
    const __nv_bfloat16* __restrict__ Vth, const __nv_bfloat16* __restrict__ Vtl,
    __nv_bfloat16* __restrict__ a2h, __nv_bfloat16* __restrict__ a2l)
{
    extern __shared__ char sm[];
    const int tid  = threadIdx.x;
    const int lane = tid & 31;
    const int wid  = tid >> 5;
    const int g    = lane >> 2;
    const int tig  = lane & 3;
    const int qm   = wid >> 1;          // 0..3 -> q rows qm*32..+32
    const int kvw  = wid & 1;           // 0..1 -> kv cols kvw*64..+64
    const int qt   = blockIdx.x;
    const int bh   = blockIdx.y;
    const int b    = bh >> 4, h = bh & 15;
    const uint32_t smb = smem_u32(sm);

    const long long qkBase = (long long)bh * SS * QKD;
    const __nv_bfloat16* QhB = Qh + qkBase + (long long)qt * 128 * QKD;
    const __nv_bfloat16* QlB = Ql + qkBase + (long long)qt * 128 * QKD;
    const __nv_bfloat16* KhB = Kh + qkBase;
    const __nv_bfloat16* KlB = Kl + qkBase;
    const __nv_bfloat16* VhB = Vth + (long long)bh * VDIM * SS;
    const __nv_bfloat16* VlB = Vtl + (long long)bh * VDIM * SS;

    // ---- Q load (once): 6 d-chunks hi/lo ----
    {
#pragma unroll
        for (int c = 0; c < 6; c++) {
#pragma unroll
            for (int it = 0; it < 2; it++) {
                int u = tid + (it << 8);
                int r = u >> 2, sg = u & 3;
                int p = sg ^ ((r >> 1) & 3);
                uint32_t d = smb + (uint32_t)(c * 8192 + r * 64 + p * 16);
                long long off = (long long)r * QKD + c * 32 + sg * 8;
                cp16(d,          QhB + off);
                cp16(d + FA_QLO, QlB + off);
            }
        }
        asm volatile("cp.async.commit_group;" ::: "memory");
    }
    fa_issueK(smb, 0, KhB, KlB, 0, tid);
    fa_issueK(smb, 1, KhB, KlB, 1, tid);

    float sacc[2][8][4], oacc[2][16][4];
    float rm[2][2], rl[2][2];
#pragma unroll
    for (int mf = 0; mf < 2; mf++) {
        rm[mf][0] = -1e30f; rm[mf][1] = -1e30f;
        rl[mf][0] = 0.f;    rl[mf][1] = 0.f;
#pragma unroll
        for (int nf = 0; nf < 16; nf++)
#pragma unroll
            for (int q = 0; q < 4; q++) oacc[mf][nf][q] = 0.f;
    }

    const int l15 = lane & 15;
    const int l7  = lane & 7;
    const uint32_t aSel = (uint32_t)(lane >> 4);
    const uint32_t bSel = (uint32_t)(l15 >> 3);
    const uint32_t swzA = (uint32_t)((l15 >> 1) & 3);
    const uint32_t swzB = (uint32_t)((l7 >> 1) & 3);
    const uint32_t aRow = smb + (uint32_t)((qm * 32 + l15) * 64);
    const uint32_t kRow = smb + FA_KOFF + (uint32_t)((kvw * 64 + l7) * 64);
    const uint32_t vRow = smb + FA_VOFF + (uint32_t)(l7 * 64);

    for (int j = 0; j < 16; j++) {
        __syncthreads();                       // PV(j-1) readers done before V overwrite
        fa_issueV(smb, VhB, VlB, j, tid);

#pragma unroll
        for (int mf = 0; mf < 2; mf++)
#pragma unroll
            for (int nf = 0; nf < 8; nf++) {
                sacc[mf][nf][0] = 0.f; sacc[mf][nf][1] = 0.f;
                sacc[mf][nf][2] = 0.f; sacc[mf][nf][3] = 0.f;
            }

        for (int c = 0; c < 6; c++) {
            const int gc = j * 6 + c;
            if (c < 2) asm volatile("cp.async.wait_group 2;" ::: "memory");
            else       asm volatile("cp.async.wait_group 1;" ::: "memory");
            __syncthreads();

            const int gcI = gc + 2;
            if (gcI < 96) {
                const int jI = gcI / 6, cI = gcI % 6;
                fa_issueK(smb, gcI % 3,
                          KhB + (long long)jI * 128 * QKD,
                          KlB + (long long)jI * 128 * QKD, cI, tid);
            } else {
                asm volatile("cp.async.commit_group;" ::: "memory");
            }

            const uint32_t aB = aRow + (uint32_t)(c * 8192);
            const uint32_t kB = kRow + (uint32_t)((gc % 3) * 16384);
#pragma unroll
            for (int kk = 0; kk < 2; kk++) {
                const uint32_t cA = (uint32_t)(kk * 2) + aSel;
                const uint32_t cB = (uint32_t)(kk * 2) + bSel;
                unsigned ah[2][4], al[2][4];
#pragma unroll
                for (int mf = 0; mf < 2; mf++) {
                    uint32_t aAd = aB + (uint32_t)(mf * 1024) + ((cA ^ swzA) << 4);
                    LDMX4(ah[mf], aAd);
                    LDMX4(al[mf], aAd + FA_QLO);
                }
#pragma unroll
                for (int nf = 0; nf < 8; nf++) {
                    uint32_t bAd = kB + (uint32_t)(nf * 512) + ((cB ^ swzB) << 4);
                    unsigned kh2[2], kl2[2];
                    LDMX2(kh2, bAd);
                    LDMX2(kl2, bAd + 8192u);
#pragma unroll
                    for (int mf = 0; mf < 2; mf++) {
                        MMA16816(sacc[mf][nf], ah[mf], kh2);
                        MMA16816(sacc[mf][nf], ah[mf], kl2);
                        MMA16816(sacc[mf][nf], al[mf], kh2);
                    }
                }
            }
        }

        // ---- online softmax (per mf; warp-local over this warp's 64 kv cols) ----
#pragma unroll
        for (int mf = 0; mf < 2; mf++) {
            float mx0 = -1e30f, mx1 = -1e30f;
#pragma unroll
            for (int nf = 0; nf < 8; nf++) {
                mx0 = fmaxf(mx0, fmaxf(sacc[mf][nf][0], sacc[mf][nf][1]));
                mx1 = fmaxf(mx1, fmaxf(sacc[mf][nf][2], sacc[mf][nf][3]));
            }
            mx0 = fmaxf(mx0, __shfl_xor_sync(0xffffffffu, mx0, 1));
            mx0 = fmaxf(mx0, __shfl_xor_sync(0xffffffffu, mx0, 2));
            mx1 = fmaxf(mx1, __shfl_xor_sync(0xffffffffu, mx1, 1));
            mx1 = fmaxf(mx1, __shfl_xor_sync(0xffffffffu, mx1, 2));
            const float mn0 = fmaxf(rm[mf][0], mx0 * ATT_SCALE);
            const float mn1 = fmaxf(rm[mf][1], mx1 * ATT_SCALE);
            const float cf0 = __expf(rm[mf][0] - mn0);
            const float cf1 = __expf(rm[mf][1] - mn1);
            float s0 = 0.f, s1 = 0.f;
#pragma unroll
            for (int nf = 0; nf < 8; nf++) {
                float p0 = __expf(sacc[mf][nf][0] * ATT_SCALE - mn0);
                float p1 = __expf(sacc[mf][nf][1] * ATT_SCALE - mn0);
                float p2 = __expf(sacc[mf][nf][2] * ATT_SCALE - mn1);
                float p3 = __expf(sacc[mf][nf][3] * ATT_SCALE - mn1);
                sacc[mf][nf][0] = p0; sacc[mf][nf][1] = p1;
                sacc[mf][nf][2] = p2; sacc[mf][nf][3] = p3;
                s0 += p0 + p1; s1 += p2 + p3;
            }
            s0 += __shfl_xor_sync(0xffffffffu, s0, 1);
            s0 += __shfl_xor_sync(0xffffffffu, s0, 2);
            s1 += __shfl_xor_sync(0xffffffffu, s1, 1);
            s1 += __shfl_xor_sync(0xffffffffu, s1, 2);
            rl[mf][0] = rl[mf][0] * cf0 + s0;
            rl[mf][1] = rl[mf][1] * cf1 + s1;
            rm[mf][0] = mn0; rm[mf][1] = mn1;
#pragma unroll
            for (int nf = 0; nf < 16; nf++) {
                oacc[mf][nf][0] *= cf0; oacc[mf][nf][1] *= cf0;
                oacc[mf][nf][2] *= cf1; oacc[mf][nf][3] *= cf1;
            }
        }

        // ---- PV: P from registers, V frags shared across both mf ----
#pragma unroll
        for (int kc = 0; kc < 4; kc++) {
            unsigned pah[2][4], pal[2][4];
#pragma unroll
            for (int mf = 0; mf < 2; mf++) {
                packP(sacc[mf][2 * kc][0],     sacc[mf][2 * kc][1],     pah[mf][0], pal[mf][0]);
                packP(sacc[mf][2 * kc][2],     sacc[mf][2 * kc][3],     pah[mf][1], pal[mf][1]);
                packP(sacc[mf][2 * kc + 1][0], sacc[mf][2 * kc + 1][1], pah[mf][2], pal[mf][2]);
                packP(sacc[mf][2 * kc + 1][2], sacc[mf][2 * kc + 1][3], pah[mf][3], pal[mf][3]);
            }
            const int cb = kvw * 2 + (kc >> 1);
            const uint32_t vB = vRow + (uint32_t)(cb * 16384);
            const uint32_t cV = (uint32_t)((kc & 1) * 2) + bSel;
#pragma unroll
            for (int nf = 0; nf < 16; nf++) {
                uint32_t bAd = vB + (uint32_t)(nf * 512) + ((cV ^ swzB) << 4);
                unsigned vh2[2], vl2[2];
                LDMX2(vh2, bAd);
                LDMX2(vl2, bAd + 8192u);
#pragma unroll
                for (int mf = 0; mf < 2; mf++) {
                    MMA16816(oacc[mf][nf], pah[mf], vh2);
                    MMA16816(oacc[mf][nf], pah[mf], vl2);
                    MMA16816(oacc[mf][nf], pal[mf], vh2);
                }
            }
        }
    }

    // ---- merge kv halves through smem, then write output ----
    __syncthreads();
    float* ex = (float*)sm;
    const int slot = qm * 32 + lane;             // 0..127
    if (kvw == 1) {
#pragma unroll
        for (int mf = 0; mf < 2; mf++)
#pragma unroll
            for (int nf = 0; nf < 16; nf++)
#pragma unroll
                for (int q = 0; q < 4; q++)
                    ex[(mf * 64 + nf * 4 + q) * 128 + slot] = oacc[mf][nf][q];
#pragma unroll
        for (int mf = 0; mf < 2; mf++) {
            ex[(128 + mf * 2 + 0) * 128 + slot] = rm[mf][0];
            ex[(128 + mf * 2 + 1) * 128 + slot] = rm[mf][1];
            ex[(132 + mf * 2 + 0) * 128 + slot] = rl[mf][0];
            ex[(132 + mf * 2 + 1) * 128 + slot] = rl[mf][1];
        }
    }
    __syncthreads();
    if (kvw == 0) {
#pragma unroll
        for (int mf = 0; mf < 2; mf++) {
            const float mo0 = ex[(128 + mf * 2 + 0) * 128 + slot];
            const float mo1 = ex[(128 + mf * 2 + 1) * 128 + slot];
            const float lo0 = ex[(132 + mf * 2 + 0) * 128 + slot];
            const float lo1 = ex[(132 + mf * 2 + 1) * 128 + slot];
            const float M0 = fmaxf(rm[mf][0], mo0);
            const float M1 = fmaxf(rm[mf][1], mo1);
            const float cs0 = __expf(rm[mf][0] - M0), co0 = __expf(mo0 - M0);
            const float cs1 = __expf(rm[mf][1] - M1), co1 = __expf(mo1 - M1);
            const float inv0 = 1.f / (rl[mf][0] * cs0 + lo0 * co0);
            const float inv1 = 1.f / (rl[mf][1] * cs1 + lo1 * co1);
            const int srow = qt * 128 + qm * 32 + mf * 16 + g;
            const long long base0 = ((long long)(b * SS) + srow) * (HH * VDIM) + h * VDIM;
            const long long base1 = base0 + 8ll * (HH * VDIM);
#pragma unroll
            for (int nf = 0; nf < 16; nf++) {
                const int d = nf * 8 + 2 * tig;
                float o0 = (oacc[mf][nf][0] * cs0 +
                            ex[(mf * 64 + nf * 4 + 0) * 128 + slot] * co0) * inv0;
                float o1 = (oacc[mf][nf][1] * cs0 +
                            ex[(mf * 64 + nf * 4 + 1) * 128 + slot] * co0) * inv0;
                unsigned hh, ll;
                packP(o0, o1, hh, ll);
                *(unsigned*)(a2h + base0 + d) = hh;
                *(unsigned*)(a2l + base0 + d) = ll;
                float o2 = (oacc[mf][nf][2] * cs1 +
                            ex[(mf * 64 + nf * 4 + 2) * 128 + slot] * co1) * inv1;
                float o3 = (oacc[mf][nf][3] * cs1 +
                            ex[(mf * 64 + nf * 4 + 3) * 128 + slot] * co1) * inv1;
                packP(o2, o3, hh, ll);
                *(unsigned*)(a2h + base1 + d) = hh;
                *(unsigned*)(a2l + base1 + d) = ll;
            }
        }
    }
}

// ---------------- fp32 -> bf16 hi/lo converter ----------------
__global__ void convert_kernel(const float* __restrict__ in,
                               __nv_bfloat16* __restrict__ hp,
                               __nv_bfloat16* __restrict__ lp, long long n4)
{
    for (long long i = (long long)blockIdx.x * 256 + threadIdx.x; i < n4;
         i += (long long)gridDim.x * 256) {
        float4 v = ((const float4*)in)[i];
        __nv_bfloat16 h0, h1, h2, h3, l0, l1, l2, l3;
        split2(v.x, h0, l0); split2(v.y, h1, l1);
        split2(v.z, h2, l2); split2(v.w, h3, l3);
        uint2 hh, ll;
        hh.x = ((unsigned)__bfloat16_as_ushort(h1) << 16) | __bfloat16_as_ushort(h0);
        hh.y = ((unsigned)__bfloat16_as_ushort(h3) << 16) | __bfloat16_as_ushort(h2);
        ll.x = ((unsigned)__bfloat16_as_ushort(l1) << 16) | __bfloat16_as_ushort(l0);
        ll.y = ((unsigned)__bfloat16_as_ushort(l3) << 16) | __bfloat16_as_ushort(l2);
        ((uint2*)hp)[i] = hh;
        ((uint2*)lp)[i] = ll;
    }
}

// ---------------- rmsnorm over KV_RANK -> bf16 hi/lo ----------------
__global__ void rmsnorm_kernel(const float* __restrict__ kv_all,
                               const float* __restrict__ w,
                               __nv_bfloat16* __restrict__ oh,
                               __nv_bfloat16* __restrict__ ol)
{
    const int row = blockIdx.x;
    const float* x = kv_all + (long long)row * KV_A;
    __shared__ float red[256];
    float ss = 0.f;
    for (int i = threadIdx.x; i < KV_RANK; i += 256) { float v = x[i]; ss += v * v; }
    red[threadIdx.x] = ss; __syncthreads();
    for (int st = 128; st > 0; st >>= 1) {
        if (threadIdx.x < st) red[threadIdx.x] += red[threadIdx.x + st];
        __syncthreads();
    }
    float scale = rsqrtf(red[0] / (float)KV_RANK + EPSV);
    for (int i = threadIdx.x; i < KV_RANK; i += 256) {
        float v = x[i] * scale * w[i];
        __nv_bfloat16 h, l; split2(v, h, l);
        oh[(long long)row * KV_RANK + i] = h;
        ol[(long long)row * KV_RANK + i] = l;
    }
}

// ---------------- RoPE + layout prep -> bf16 hi/lo ----------------
__global__ void prepare_kernel(const float* __restrict__ qraw,
                               const float* __restrict__ kvall,
                               const float* __restrict__ kvproj,
                               const float* __restrict__ cosb,
                               const float* __restrict__ sinb,
                               __nv_bfloat16* __restrict__ Qh, __nv_bfloat16* __restrict__ Ql,
                               __nv_bfloat16* __restrict__ Kh, __nv_bfloat16* __restrict__ Kl,
                               __nv_bfloat16* __restrict__ Vth, __nv_bfloat16* __restrict__ Vtl)
{
    const int bs = blockIdx.x;
    const int b = bs / SS, s = bs % SS;
    const float* cs = cosb + (long long)s * ROPE;
    const float* sn = sinb + (long long)s * ROPE;

    __shared__ float kpe[ROPE];
    if (threadIdx.x < ROPE) {
        int j = threadIdx.x;
        const float* kp = kvall + (long long)bs * KV_A + KV_RANK;
        float x  = kp[j];
        float xr = (j < 32) ? -kp[j + 32] : kp[j - 32];
        kpe[j] = x * cs[j] + xr * sn[j];
    }
    __syncthreads();

    const float* qrow = qraw + (long long)bs * (HH * QKD);
    const float* prow = kvproj + (long long)bs * KV_PROJ;

    for (int idx = threadIdx.x; idx < HH * QKD; idx += blockDim.x) {
        int h = idx / QKD, d = idx % QKD;
        long long off = (((long long)(b * HH + h)) * SS + s) * QKD + d;
        float qv;
        if (d < NOPE) {
            qv = qrow[h * QKD + d];
        } else {
            int j = d - NOPE;
            float x  = qrow[h * QKD + NOPE + j];
            float xr = (j < 32) ? -qrow[h * QKD + NOPE + j + 32]
                                :  qrow[h * QKD + NOPE + j - 32];
            qv = x * cs[j] + xr * sn[j];
        }
        __nv_bfloat16 hh, ll;
        split2(qv, hh, ll); Qh[off] = hh; Ql[off] = ll;
        float kv = (d < NOPE) ? prow[h * (NOPE + VDIM) + d] : kpe[d - NOPE];
        split2(kv, hh, ll); Kh[off] = hh; Kl[off] = ll;
    }
    for (int idx = threadIdx.x; idx < HH * VDIM; idx += blockDim.x) {
        int h = idx / VDIM, d = idx % VDIM;
        long long off = (((long long)(b * HH + h)) * VDIM + d) * SS + s;
        float v = prow[h * (NOPE + VDIM) + NOPE + d];
        __nv_bfloat16 hh, ll; split2(v, hh, ll);
        Vth[off] = hh; Vtl[off] = ll;
    }
}

// ---------------- launch ----------------
extern "C" void kernel_launch(void* const* d_in, const int* in_sizes, int n_in,
                              void* d_out, int out_size)
{
    const float* x    = (const float*)d_in[0];
    const float* cosb = (const float*)d_in[1];
    const float* sinb = (const float*)d_in[2];
    const float* wq   = (const float*)d_in[3];
    const float* wkva = (const float*)d_in[4];
    const float* kvw  = (const float*)d_in[5];
    const float* wkvb = (const float*)d_in[6];
    const float* wo   = (const float*)d_in[7];
    float* out = (float*)d_out;

    cudaFuncSetAttribute(gemm3, cudaFuncAttributeMaxDynamicSharedMemorySize, GEMM3_SMEM);
    cudaFuncSetAttribute(fa_kernel, cudaFuncAttributeMaxDynamicSharedMemorySize, FA_SMEM);

    float *qraw, *kvall, *kvproj;
    cudaGetSymbolAddress((void**)&qraw,   g_qraw);
    cudaGetSymbolAddress((void**)&kvall,  g_kvall);
    cudaGetSymbolAddress((void**)&kvproj, g_kvproj);

    __nv_bfloat16 *xh, *xl, *wqh, *wql, *wkvah, *wkval, *wkvbh, *wkvbl, *woh, *wol;
    __nv_bfloat16 *kvnh, *kvnl, *Qh, *Ql, *Kh, *Kl, *Vth, *Vtl, *a2h, *a2l;
    cudaGetSymbolAddress((void**)&xh,    g_xh);    cudaGetSymbolAddress((void**)&xl,    g_xl);
    cudaGetSymbolAddress((void**)&wqh,   g_wqh);   cudaGetSymbolAddress((void**)&wql,   g_wql);
    cudaGetSymbolAddress((void**)&wkvah, g_wkvah); cudaGetSymbolAddress((void**)&wkval, g_wkval);
    cudaGetSymbolAddress((void**)&wkvbh, g_wkvbh); cudaGetSymbolAddress((void**)&wkvbl, g_wkvbl);
    cudaGetSymbolAddress((void**)&woh,   g_woh);   cudaGetSymbolAddress((void**)&wol,   g_wol);
    cudaGetSymbolAddress((void**)&kvnh,  g_kvnh);  cudaGetSymbolAddress((void**)&kvnl,  g_kvnl);
    cudaGetSymbolAddress((void**)&Qh,    g_Qh);    cudaGetSymbolAddress((void**)&Ql,    g_Ql);
    cudaGetSymbolAddress((void**)&Kh,    g_Kh);    cudaGetSymbolAddress((void**)&Kl,    g_Kl);
    cudaGetSymbolAddress((void**)&Vth,   g_Vth);   cudaGetSymbolAddress((void**)&Vtl,   g_Vtl);
    cudaGetSymbolAddress((void**)&a2h,   g_a2h);   cudaGetSymbolAddress((void**)&a2l,   g_a2l);

    const int M = BB * SS;   // 4096

    // 0) pre-split inputs/weights to bf16 hi/lo
    convert_kernel<<<1024, 256>>>(x,    xh,    xl,    (long long)BB * SS * DD / 4);
    convert_kernel<<<1024, 256>>>(wq,   wqh,   wql,   (long long)(HH * QKD) * DD / 4);
    convert_kernel<<<1024, 256>>>(wkva, wkvah, wkval, (long long)KV_A * DD / 4);
    convert_kernel<<<1024, 256>>>(wkvb, wkvbh, wkvbl, (long long)KV_PROJ * KV_RANK / 4);
    convert_kernel<<<1024, 256>>>(wo,   woh,   wol,   (long long)DD * DD / 4);

    // 1) q_raw = X @ wq^T        [4096,3072] K=2048
    gemm3<<<dim3(3072 / 128, M / 128, 1), 256, GEMM3_SMEM>>>(
        xh, xl, wqh, wql, qraw, M, HH * QKD, DD, DD, DD, HH * QKD, 0, 0, 0, 1.f);

    // 2) kv_all = X @ wkv_a^T    [4096,576] K=2048
    gemm3<<<dim3((KV_A + 127) / 128, M / 128, 1), 256, GEMM3_SMEM>>>(
        xh, xl, wkvah, wkval, kvall, M, KV_A, DD, DD, DD, KV_A, 0, 0, 0, 1.f);

    // 3) rmsnorm -> bf16 hi/lo
    rmsnorm_kernel<<<M, 256>>>(kvall, kvw, kvnh, kvnl);

    // 4) kv_proj = kvn @ wkv_b^T [4096,4096] K=512
    gemm3<<<dim3(KV_PROJ / 128, M / 128, 1), 256, GEMM3_SMEM>>>(
        kvnh, kvnl, wkvbh, wkvbl, kvproj, M, KV_PROJ, KV_RANK,
        KV_RANK, KV_RANK, KV_PROJ, 0, 0, 0, 1.f);

    // 5) RoPE + layout -> bf16 hi/lo Q/K/Vt
    prepare_kernel<<<M, 256>>>(qraw, kvall, kvproj, cosb, sinb, Qh, Ql, Kh, Kl, Vth, Vtl);

    // 6) fused attention (QK^T, online softmax, PV, regroup) -> a2h/a2l
    fa_kernel<<<dim3(SS / 128, BB * HH, 1), 256, FA_SMEM>>>(
        Qh, Ql, Kh, Kl, Vth, Vtl, a2h, a2l);

    // 7) out = attn2 @ wo^T      [4096,2048] K=2048
    gemm3<<<dim3(DD / 128, M / 128, 1), 256, GEMM3_SMEM>>>(
        a2h, a2l, woh, wol, out, M, DD, HH * VDIM,
        HH * VDIM, HH * VDIM, DD, 0, 0, 0, 1.f);
}

// round 13
// speedup vs baseline: 1.0544x; 1.0544x over previous
#include <cuda_runtime.h>
#include <cuda_bf16.h>
#include <cstdint>

// ---------------- problem constants ----------------
#define BB 2
#define SS 2048
#define DD 2048
#define HH 16
#define NOPE 128
#define ROPE 64
#define VDIM 128
#define QKD 192           // NOPE + ROPE
#define KV_RANK 512
#define KV_A (KV_RANK + ROPE)   // 576
#define KV_PROJ (HH * (NOPE + VDIM)) // 4096
#define QKV_N (HH * QKD + KV_A)      // 3648 (merged q + kv_a projection)
#define EPSV 1e-6f
#define ATT_SCALE 0.07216878364870323f  // 192^-0.5

// ---------------- fp32 scratch ----------------
__device__ __align__(16) float g_qkv   [(size_t)BB * SS * QKV_N];   // [B,S,3648]
__device__ __align__(16) float g_kvproj[(size_t)BB * SS * KV_PROJ];

// ---------------- bf16 hi/lo scratch ----------------
__device__ __align__(16) __nv_bfloat16 g_xh    [(size_t)BB * SS * DD];
__device__ __align__(16) __nv_bfloat16 g_xl    [(size_t)BB * SS * DD];
__device__ __align__(16) __nv_bfloat16 g_wqkvh [(size_t)QKV_N * DD];
__device__ __align__(16) __nv_bfloat16 g_wqkvl [(size_t)QKV_N * DD];
__device__ __align__(16) __nv_bfloat16 g_wkvbh [(size_t)KV_PROJ * KV_RANK];
__device__ __align__(16) __nv_bfloat16 g_wkvbl [(size_t)KV_PROJ * KV_RANK];
__device__ __align__(16) __nv_bfloat16 g_woh   [(size_t)DD * DD];
__device__ __align__(16) __nv_bfloat16 g_wol   [(size_t)DD * DD];
__device__ __align__(16) __nv_bfloat16 g_kvnh  [(size_t)BB * SS * KV_RANK];
__device__ __align__(16) __nv_bfloat16 g_kvnl  [(size_t)BB * SS * KV_RANK];
__device__ __align__(16) __nv_bfloat16 g_Qh    [(size_t)BB * HH * SS * QKD];
__device__ __align__(16) __nv_bfloat16 g_Ql    [(size_t)BB * HH * SS * QKD];
__device__ __align__(16) __nv_bfloat16 g_Kh    [(size_t)BB * HH * SS * QKD];
__device__ __align__(16) __nv_bfloat16 g_Kl    [(size_t)BB * HH * SS * QKD];
__device__ __align__(16) __nv_bfloat16 g_Vth   [(size_t)BB * HH * VDIM * SS];
__device__ __align__(16) __nv_bfloat16 g_Vtl   [(size_t)BB * HH * VDIM * SS];
__device__ __align__(16) __nv_bfloat16 g_a2h   [(size_t)BB * SS * HH * VDIM];
__device__ __align__(16) __nv_bfloat16 g_a2l   [(size_t)BB * SS * HH * VDIM];

// ---------------- helpers ----------------
__device__ __forceinline__ uint32_t smem_u32(const void* p) {
    uint32_t a;
    asm("{ .reg .u64 t; cvta.to.shared.u64 t, %1; cvt.u32.u64 %0, t; }" : "=r"(a) : "l"(p));
    return a;
}
__device__ __forceinline__ void split2(float x, __nv_bfloat16& h, __nv_bfloat16& l) {
    h = __float2bfloat16_rn(x);
    l = __float2bfloat16_rn(x - __bfloat162float(h));
}
__device__ __forceinline__ void packP(float a, float b, unsigned& hi, unsigned& lo) {
    __nv_bfloat16 ha = __float2bfloat16_rn(a);
    __nv_bfloat16 hb = __float2bfloat16_rn(b);
    __nv_bfloat16 la = __float2bfloat16_rn(a - __bfloat162float(ha));
    __nv_bfloat16 lb = __float2bfloat16_rn(b - __bfloat162float(hb));
    hi = ((unsigned)__bfloat16_as_ushort(hb) << 16) | __bfloat16_as_ushort(ha);
    lo = ((unsigned)__bfloat16_as_ushort(lb) << 16) | __bfloat16_as_ushort(la);
}
__device__ __forceinline__ void cp16(uint32_t d, const void* s) {
    asm volatile("cp.async.cg.shared.global [%0], [%1], 16;" :: "r"(d), "l"(s));
}
__device__ __forceinline__ void cp16z(uint32_t d, const void* s, unsigned bytes) {
    asm volatile("cp.async.cg.shared.global [%0], [%1], 16, %2;" :: "r"(d), "l"(s), "r"(bytes));
}

#define MMA16816(d, a, b) \
    asm volatile("mma.sync.aligned.m16n8k16.row.col.f32.bf16.bf16.f32 " \
                 "{%0,%1,%2,%3}, {%4,%5,%6,%7}, {%8,%9}, {%0,%1,%2,%3};" \
                 : "+f"((d)[0]), "+f"((d)[1]), "+f"((d)[2]), "+f"((d)[3]) \
                 : "r"((a)[0]), "r"((a)[1]), "r"((a)[2]), "r"((a)[3]), \
                   "r"((b)[0]), "r"((b)[1]))

#define LDMX4(r, ad) \
    asm volatile("ldmatrix.sync.aligned.m8n8.x4.shared.b16 {%0,%1,%2,%3}, [%4];" \
                 : "=r"((r)[0]), "=r"((r)[1]), "=r"((r)[2]), "=r"((r)[3]) : "r"(ad))
#define LDMX2(r, ad) \
    asm volatile("ldmatrix.sync.aligned.m8n8.x2.shared.b16 {%0,%1}, [%2];" \
                 : "=r"((r)[0]), "=r"((r)[1]) : "r"(ad))

// ======== bf16x3 GEMM: CTA 128x128, warp 64x32, 3-stage cp.async (R8) =========
#define MOFF 8192u
#define STG  32768u
#define GEMM3_SMEM 98304

__device__ __forceinline__ void g3_issue(
    uint32_t sb,
    const __nv_bfloat16* __restrict__ Ah, const __nv_bfloat16* __restrict__ Al,
    const __nv_bfloat16* __restrict__ Bh, const __nv_bfloat16* __restrict__ Bl,
    int bm, int bn, int N, int lda, int ldb, int k0, int tid)
{
#pragma unroll
    for (int half = 0; half < 2; half++) {
        int r  = (tid >> 2) + half * 64;
        int sg = tid & 3;
        int p  = sg ^ ((r >> 1) & 3);
        uint32_t d = sb + (uint32_t)(r * 64 + p * 16);
        long long ko = (long long)k0 + sg * 8;
        cp16(d,        Ah + (long long)(bm + r) * lda + ko);
        cp16(d + MOFF, Al + (long long)(bm + r) * lda + ko);
        int gn = bn + r;
        unsigned bytes = (gn < N) ? 16u : 0u;
        int gr = (gn < N) ? gn : 0;
        cp16z(d + 2 * MOFF, Bh + (long long)gr * ldb + ko, bytes);
        cp16z(d + 3 * MOFF, Bl + (long long)gr * ldb + ko, bytes);
    }
    asm volatile("cp.async.commit_group;" ::: "memory");
}

__global__ __launch_bounds__(256, 2) void gemm3(
    const __nv_bfloat16* __restrict__ Ah, const __nv_bfloat16* __restrict__ Al,
    const __nv_bfloat16* __restrict__ Bh, const __nv_bfloat16* __restrict__ Bl,
    float* __restrict__ C,
    int M, int N, int K, int lda, int ldb, int ldc,
    long long sA, long long sB, long long sC, float alpha)
{
    extern __shared__ char sm[];
    const int z = blockIdx.z;
    Ah += z * sA; Al += z * sA; Bh += z * sB; Bl += z * sB; C += z * sC;

    const int tid  = threadIdx.x;
    const int lane = tid & 31;
    const int wid  = tid >> 5;
    const int g    = lane >> 2;
    const int tig  = lane & 3;
    const int wm   = wid >> 2;
    const int wn   = wid & 3;
    const int bm = blockIdx.y * 128;
    const int bn = blockIdx.x * 128;
    const uint32_t smb = smem_u32(sm);

    float acc[4][4][4];
#pragma unroll
    for (int i = 0; i < 4; i++)
#pragma unroll
        for (int j = 0; j < 4; j++)
#pragma unroll
            for (int q = 0; q < 4; q++) acc[i][j][q] = 0.f;

    const int nc = K >> 5;

    g3_issue(smb,       Ah, Al, Bh, Bl, bm, bn, N, lda, ldb, 0,  tid);
    g3_issue(smb + STG, Ah, Al, Bh, Bl, bm, bn, N, lda, ldb, 32, tid);

    const int l15 = lane & 15;
    const int l7  = lane & 7;
    const uint32_t aSel = (uint32_t)(lane >> 4);
    const uint32_t bSel = (uint32_t)(l15 >> 3);
    const uint32_t swzA = (uint32_t)((l15 >> 1) & 3);
    const uint32_t swzB = (uint32_t)((l7 >> 1) & 3);
    const uint32_t aBase = smb + (uint32_t)((wm * 64 + l15) * 64);
    const uint32_t bBase = smb + 2u * MOFF + (uint32_t)((wn * 32 + l7) * 64);

    for (int c = 0; c < nc; c++) {
        asm volatile("cp.async.wait_group 1;" ::: "memory");
        __syncthreads();

        if (c + 2 < nc) {
            g3_issue(smb + (uint32_t)((c + 2) % 3) * STG,
                     Ah, Al, Bh, Bl, bm, bn, N, lda, ldb, (c + 2) << 5, tid);
        } else {
            asm volatile("cp.async.commit_group;" ::: "memory");
        }

        const uint32_t so = (uint32_t)(c % 3) * STG;
#pragma unroll
        for (int kk = 0; kk < 2; kk++) {
            const uint32_t cA = (uint32_t)(kk * 2) + aSel;
            const uint32_t cB = (uint32_t)(kk * 2) + bSel;
            unsigned bh[4][2], blr[4][2];
#pragma unroll
            for (int nf = 0; nf < 4; nf++) {
                uint32_t ad = bBase + so + (uint32_t)(nf * 512) + ((cB ^ swzB) << 4);
                LDMX2(bh[nf], ad);
                LDMX2(blr[nf], ad + MOFF);
            }
#pragma unroll
            for (int mf = 0; mf < 4; mf++) {
                uint32_t ad = aBase + so + (uint32_t)(mf * 1024) + ((cA ^ swzA) << 4);
                unsigned ah[4], al[4];
                LDMX4(ah, ad);
                LDMX4(al, ad + MOFF);
#pragma unroll
                for (int nf = 0; nf < 4; nf++) {
                    MMA16816(acc[mf][nf], ah, bh[nf]);
                    MMA16816(acc[mf][nf], ah, blr[nf]);
                    MMA16816(acc[mf][nf], al, bh[nf]);
                }
            }
        }
    }

#pragma unroll
    for (int mf = 0; mf < 4; mf++) {
#pragma unroll
        for (int nf = 0; nf < 4; nf++) {
            int row = bm + wm * 64 + mf * 16 + g;
            int col = bn + wn * 32 + nf * 8 + 2 * tig;
            if (col < N) {
                float* p0 = C + (long long)row * ldc + col;
                p0[0] = alpha * acc[mf][nf][0];
                p0[1] = alpha * acc[mf][nf][1];
                float* p1 = p0 + (long long)8 * ldc;
                p1[0] = alpha * acc[mf][nf][2];
                p1[1] = alpha * acc[mf][nf][3];
            }
        }
    }
}

// ================= fused flash attention (bf16x3, online softmax) =============
// R10 layout: grid (16 q-tiles, 32 bh), 256 thr, warp = 16 q-rows x 128 kv.
// SMEM: Q 6 ch x (hi 8K | lo 8K at +49152) = 98304
//       K 3 stages x (hi 8K + lo 8K) at 98304
//       V 4 ch x (hi 8K + lo 8K) at 147456.   Total 212992.
#define FA_KOFF 98304u
#define FA_QLO  49152u
#define FA_VOFF 147456u
#define FA_SMEM 212992

__device__ __forceinline__ void fa_issueK(
    uint32_t smb, int stage,
    const __nv_bfloat16* __restrict__ Khp, const __nv_bfloat16* __restrict__ Klp,
    int c, int tid)
{
#pragma unroll
    for (int it = 0; it < 2; it++) {
        int u = tid + (it << 8);
        int r = u >> 2, sg = u & 3;
        int p = sg ^ ((r >> 1) & 3);
        uint32_t d = smb + FA_KOFF + (uint32_t)(stage * 16384 + r * 64 + p * 16);
        long long off = (long long)r * QKD + c * 32 + sg * 8;
        cp16(d,         Khp + off);
        cp16(d + 8192u, Klp + off);
    }
    asm volatile("cp.async.commit_group;" ::: "memory");
}

__device__ __forceinline__ void fa_issueV(
    uint32_t smb,
    const __nv_bfloat16* __restrict__ Vhp, const __nv_bfloat16* __restrict__ Vlp,
    int j, int tid)
{
#pragma unroll
    for (int it = 0; it < 8; it++) {
        int u = tid + (it << 8);            // 0..2047
        int cb = u >> 9, v = u & 511;
        int r = v >> 2, sg = v & 3;
        int p = sg ^ ((r >> 1) & 3);
        uint32_t d = smb + FA_VOFF + (uint32_t)(cb * 16384 + r * 64 + p * 16);
        long long off = (long long)r * SS + j * 128 + cb * 32 + sg * 8;
        cp16(d,         Vhp + off);
        cp16(d + 8192u, Vlp + off);
    }
    asm volatile("cp.async.commit_group;" ::: "memory");
}

__global__ __launch_bounds__(256, 1) void fa_kernel(
    const __nv_bfloat16* __restrict__ Qh, const __nv_bfloat16* __restrict__ Ql,
    const __nv_bfloat16* __restrict__ Kh, const __nv_bfloat16* __restrict__ Kl,
    const __nv_bfloat16* __restrict__ Vth, const __nv_bfloat16* __restrict__ Vtl,
    __nv_bfloat16* __restrict__ a2h, __nv_bfloat16* __restrict__ a2l)
{
    extern __shared__ char sm[];
    const int tid  = threadIdx.x;
    const int lane = tid & 31;
    const int wid  = tid >> 5;
    const int g    = lane >> 2;
    const int tig  = lane & 3;
    const int qt   = blockIdx.x;
    const int bh   = blockIdx.y;
    const int b    = bh >> 4, h = bh & 15;
    const uint32_t smb = smem_u32(sm);

    const long long qkBase = (long long)bh * SS * QKD;
    const __nv_bfloat16* QhB = Qh + qkBase + (long long)qt * 128 * QKD;
    const __nv_bfloat16* QlB = Ql + qkBase + (long long)qt * 128 * QKD;
    const __nv_bfloat16* KhB = Kh + qkBase;
    const __nv_bfloat16* KlB = Kl + qkBase;
    const __nv_bfloat16* VhB = Vth + (long long)bh * VDIM * SS;
    const __nv_bfloat16* VlB = Vtl + (long long)bh * VDIM * SS;

    // ---- Q load (once): 6 d-chunks hi/lo ----
    {
#pragma unroll
        for (int c = 0; c < 6; c++) {
#pragma unroll
            for (int it = 0; it < 2; it++) {
                int u = tid + (it << 8);
                int r = u >> 2, sg = u & 3;
                int p = sg ^ ((r >> 1) & 3);
                uint32_t d = smb + (uint32_t)(c * 8192 + r * 64 + p * 16);
                long long off = (long long)r * QKD + c * 32 + sg * 8;
                cp16(d,          QhB + off);
                cp16(d + FA_QLO, QlB + off);
            }
        }
        asm volatile("cp.async.commit_group;" ::: "memory");
    }
    fa_issueK(smb, 0, KhB, KlB, 0, tid);
    fa_issueK(smb, 1, KhB, KlB, 1, tid);

    float sacc[16][4], oacc[16][4];
    float m0 = -1e30f, m1 = -1e30f, l0 = 0.f, l1 = 0.f;
#pragma unroll
    for (int nf = 0; nf < 16; nf++)
#pragma unroll
        for (int q = 0; q < 4; q++) oacc[nf][q] = 0.f;

    const int l15 = lane & 15;
    const int l7  = lane & 7;
    const uint32_t aSel = (uint32_t)(lane >> 4);
    const uint32_t bSel = (uint32_t)(l15 >> 3);
    const uint32_t swzA = (uint32_t)((l15 >> 1) & 3);
    const uint32_t swzB = (uint32_t)((l7 >> 1) & 3);
    const uint32_t aRow = smb + (uint32_t)((wid * 16 + l15) * 64);
    const uint32_t kRow = smb + FA_KOFF + (uint32_t)(l7 * 64);
    const uint32_t vRow = smb + FA_VOFF + (uint32_t)(l7 * 64);

    for (int j = 0; j < 16; j++) {
        __syncthreads();                       // PV(j-1) readers done before V overwrite
        fa_issueV(smb, VhB, VlB, j, tid);

#pragma unroll
        for (int nf = 0; nf < 16; nf++) {
            sacc[nf][0] = 0.f; sacc[nf][1] = 0.f; sacc[nf][2] = 0.f; sacc[nf][3] = 0.f;
        }

        for (int c = 0; c < 6; c++) {
            const int gc = j * 6 + c;
            if (c < 2) asm volatile("cp.async.wait_group 2;" ::: "memory");
            else       asm volatile("cp.async.wait_group 1;" ::: "memory");
            __syncthreads();

            const int gcI = gc + 2;
            if (gcI < 96) {
                const int jI = gcI / 6, cI = gcI % 6;
                fa_issueK(smb, gcI % 3,
                          KhB + (long long)jI * 128 * QKD,
                          KlB + (long long)jI * 128 * QKD, cI, tid);
            } else {
                asm volatile("cp.async.commit_group;" ::: "memory");
            }

            const uint32_t aB = aRow + (uint32_t)(c * 8192);
            const uint32_t kB = kRow + (uint32_t)((gc % 3) * 16384);
#pragma unroll
            for (int kk = 0; kk < 2; kk++) {
                const uint32_t cA = (uint32_t)(kk * 2) + aSel;
                const uint32_t cB = (uint32_t)(kk * 2) + bSel;
                uint32_t aAd = aB + ((cA ^ swzA) << 4);
                unsigned ah[4], al[4];
                LDMX4(ah, aAd);
                LDMX4(al, aAd + FA_QLO);
#pragma unroll
                for (int nf = 0; nf < 16; nf++) {
                    uint32_t bAd = kB + (uint32_t)(nf * 512) + ((cB ^ swzB) << 4);
                    unsigned kh2[2], kl2[2];
                    LDMX2(kh2, bAd);
                    LDMX2(kl2, bAd + 8192u);
                    MMA16816(sacc[nf], ah, kh2);
                    MMA16816(sacc[nf], ah, kl2);
                    MMA16816(sacc[nf], al, kh2);
                }
            }
        }

        // ---- online softmax (warp-local; rows g and g+8) ----
        float mx0 = -1e30f, mx1 = -1e30f;
#pragma unroll
        for (int nf = 0; nf < 16; nf++) {
            mx0 = fmaxf(mx0, fmaxf(sacc[nf][0], sacc[nf][1]));
            mx1 = fmaxf(mx1, fmaxf(sacc[nf][2], sacc[nf][3]));
        }
        mx0 = fmaxf(mx0, __shfl_xor_sync(0xffffffffu, mx0, 1));
        mx0 = fmaxf(mx0, __shfl_xor_sync(0xffffffffu, mx0, 2));
        mx1 = fmaxf(mx1, __shfl_xor_sync(0xffffffffu, mx1, 1));
        mx1 = fmaxf(mx1, __shfl_xor_sync(0xffffffffu, mx1, 2));
        const float mn0 = fmaxf(m0, mx0 * ATT_SCALE);
        const float mn1 = fmaxf(m1, mx1 * ATT_SCALE);
        const float cf0 = __expf(m0 - mn0);
        const float cf1 = __expf(m1 - mn1);
        float s0 = 0.f, s1 = 0.f;
#pragma unroll
        for (int nf = 0; nf < 16; nf++) {
            float p0 = __expf(sacc[nf][0] * ATT_SCALE - mn0);
            float p1 = __expf(sacc[nf][1] * ATT_SCALE - mn0);
            float p2 = __expf(sacc[nf][2] * ATT_SCALE - mn1);
            float p3 = __expf(sacc[nf][3] * ATT_SCALE - mn1);
            sacc[nf][0] = p0; sacc[nf][1] = p1; sacc[nf][2] = p2; sacc[nf][3] = p3;
            s0 += p0 + p1; s1 += p2 + p3;
        }
        s0 += __shfl_xor_sync(0xffffffffu, s0, 1);
        s0 += __shfl_xor_sync(0xffffffffu, s0, 2);
        s1 += __shfl_xor_sync(0xffffffffu, s1, 1);
        s1 += __shfl_xor_sync(0xffffffffu, s1, 2);
        l0 = l0 * cf0 + s0; l1 = l1 * cf1 + s1;
        m0 = mn0; m1 = mn1;
#pragma unroll
        for (int nf = 0; nf < 16; nf++) {
            oacc[nf][0] *= cf0; oacc[nf][1] *= cf0;
            oacc[nf][2] *= cf1; oacc[nf][3] *= cf1;
        }

        // ---- PV: P from registers (acc->A frag remap), V from smem ----
#pragma unroll
        for (int kc = 0; kc < 8; kc++) {
            unsigned ah[4], al[4];
            packP(sacc[2 * kc][0],     sacc[2 * kc][1],     ah[0], al[0]);
            packP(sacc[2 * kc][2],     sacc[2 * kc][3],     ah[1], al[1]);
            packP(sacc[2 * kc + 1][0], sacc[2 * kc + 1][1], ah[2], al[2]);
            packP(sacc[2 * kc + 1][2], sacc[2 * kc + 1][3], ah[3], al[3]);
            const uint32_t vB = vRow + (uint32_t)((kc >> 1) * 16384);
            const uint32_t cV = (uint32_t)((kc & 1) * 2) + bSel;
#pragma unroll
            for (int nf = 0; nf < 16; nf++) {
                uint32_t bAd = vB + (uint32_t)(nf * 512) + ((cV ^ swzB) << 4);
                unsigned vh2[2], vl2[2];
                LDMX2(vh2, bAd);
                LDMX2(vl2, bAd + 8192u);
                MMA16816(oacc[nf], ah, vh2);
                MMA16816(oacc[nf], ah, vl2);
                MMA16816(oacc[nf], al, vh2);
            }
        }
    }

    // ---- epilogue: normalize, split hi/lo, write a2 (regroup fused) ----
    const float li0 = 1.f / l0, li1 = 1.f / l1;
    const int srow = qt * 128 + wid * 16 + g;
    const long long base0 = ((long long)(b * SS) + srow) * (HH * VDIM) + h * VDIM;
    const long long base1 = base0 + 8ll * (HH * VDIM);
#pragma unroll
    for (int nf = 0; nf < 16; nf++) {
        const int d = nf * 8 + 2 * tig;
        unsigned hh, ll;
        packP(oacc[nf][0] * li0, oacc[nf][1] * li0, hh, ll);
        *(unsigned*)(a2h + base0 + d) = hh;
        *(unsigned*)(a2l + base0 + d) = ll;
        packP(oacc[nf][2] * li1, oacc[nf][3] * li1, hh, ll);
        *(unsigned*)(a2h + base1 + d) = hh;
        *(unsigned*)(a2l + base1 + d) = ll;
    }
}

// ---------------- fp32 -> bf16 hi/lo converter ----------------
__global__ void convert_kernel(const float* __restrict__ in,
                               __nv_bfloat16* __restrict__ hp,
                               __nv_bfloat16* __restrict__ lp, long long n4)
{
    for (long long i = (long long)blockIdx.x * 256 + threadIdx.x; i < n4;
         i += (long long)gridDim.x * 256) {
        float4 v = ((const float4*)in)[i];
        __nv_bfloat16 h0, h1, h2, h3, l0, l1, l2, l3;
        split2(v.x, h0, l0); split2(v.y, h1, l1);
        split2(v.z, h2, l2); split2(v.w, h3, l3);
        uint2 hh, ll;
        hh.x = ((unsigned)__bfloat16_as_ushort(h1) << 16) | __bfloat16_as_ushort(h0);
        hh.y = ((unsigned)__bfloat16_as_ushort(h3) << 16) | __bfloat16_as_ushort(h2);
        ll.x = ((unsigned)__bfloat16_as_ushort(l1) << 16) | __bfloat16_as_ushort(l0);
        ll.y = ((unsigned)__bfloat16_as_ushort(l3) << 16) | __bfloat16_as_ushort(l2);
        ((uint2*)hp)[i] = hh;
        ((uint2*)lp)[i] = ll;
    }
}

// ---------------- rmsnorm over KV_RANK (reads merged qkv buffer) --------------
__global__ void rmsnorm_kernel(const float* __restrict__ qkv,
                               const float* __restrict__ w,
                               __nv_bfloat16* __restrict__ oh,
                               __nv_bfloat16* __restrict__ ol)
{
    const int row = blockIdx.x;
    const float* x = qkv + (long long)row * QKV_N + HH * QKD;   // kv_all[0:512]
    __shared__ float red[256];
    float ss = 0.f;
    for (int i = threadIdx.x; i < KV_RANK; i += 256) { float v = x[i]; ss += v * v; }
    red[threadIdx.x] = ss; __syncthreads();
    for (int st = 128; st > 0; st >>= 1) {
        if (threadIdx.x < st) red[threadIdx.x] += red[threadIdx.x + st];
        __syncthreads();
    }
    float scale = rsqrtf(red[0] / (float)KV_RANK + EPSV);
    for (int i = threadIdx.x; i < KV_RANK; i += 256) {
        float v = x[i] * scale * w[i];
        __nv_bfloat16 h, l; split2(v, h, l);
        oh[(long long)row * KV_RANK + i] = h;
        ol[(long long)row * KV_RANK + i] = l;
    }
}

// ---------------- RoPE + layout prep (reads merged qkv buffer) ----------------
__global__ void prepare_kernel(const float* __restrict__ qkv,
                               const float* __restrict__ kvproj,
                               const float* __restrict__ cosb,
                               const float* __restrict__ sinb,
                               __nv_bfloat16* __restrict__ Qh, __nv_bfloat16* __restrict__ Ql,
                               __nv_bfloat16* __restrict__ Kh, __nv_bfloat16* __restrict__ Kl,
                               __nv_bfloat16* __restrict__ Vth, __nv_bfloat16* __restrict__ Vtl)
{
    const int bs = blockIdx.x;
    const int b = bs / SS, s = bs % SS;
    const float* cs = cosb + (long long)s * ROPE;
    const float* sn = sinb + (long long)s * ROPE;

    __shared__ float kpe[ROPE];
    if (threadIdx.x < ROPE) {
        int j = threadIdx.x;
        const float* kp = qkv + (long long)bs * QKV_N + HH * QKD + KV_RANK;
        float x  = kp[j];
        float xr = (j < 32) ? -kp[j + 32] : kp[j - 32];
        kpe[j] = x * cs[j] + xr * sn[j];
    }
    __syncthreads();

    const float* qrow = qkv + (long long)bs * QKV_N;
    const float* prow = kvproj + (long long)bs * KV_PROJ;

    for (int idx = threadIdx.x; idx < HH * QKD; idx += blockDim.x) {
        int h = idx / QKD, d = idx % QKD;
        long long off = (((long long)(b * HH + h)) * SS + s) * QKD + d;
        float qv;
        if (d < NOPE) {
            qv = qrow[h * QKD + d];
        } else {
            int j = d - NOPE;
            float x  = qrow[h * QKD + NOPE + j];
            float xr = (j < 32) ? -qrow[h * QKD + NOPE + j + 32]
                                :  qrow[h * QKD + NOPE + j - 32];
            qv = x * cs[j] + xr * sn[j];
        }
        __nv_bfloat16 hh, ll;
        split2(qv, hh, ll); Qh[off] = hh; Ql[off] = ll;
        float kv = (d < NOPE) ? prow[h * (NOPE + VDIM) + d] : kpe[d - NOPE];
        split2(kv, hh, ll); Kh[off] = hh; Kl[off] = ll;
    }
    for (int idx = threadIdx.x; idx < HH * VDIM; idx += blockDim.x) {
        int h = idx / VDIM, d = idx % VDIM;
        long long off = (((long long)(b * HH + h)) * VDIM + d) * SS + s;
        float v = prow[h * (NOPE + VDIM) + NOPE + d];
        __nv_bfloat16 hh, ll; split2(v, hh, ll);
        Vth[off] = hh; Vtl[off] = ll;
    }
}

// ---------------- launch ----------------
extern "C" void kernel_launch(void* const* d_in, const int* in_sizes, int n_in,
                              void* d_out, int out_size)
{
    const float* x    = (const float*)d_in[0];
    const float* cosb = (const float*)d_in[1];
    const float* sinb = (const float*)d_in[2];
    const float* wq   = (const float*)d_in[3];
    const float* wkva = (const float*)d_in[4];
    const float* kvw  = (const float*)d_in[5];
    const float* wkvb = (const float*)d_in[6];
    const float* wo   = (const float*)d_in[7];
    float* out = (float*)d_out;

    cudaFuncSetAttribute(gemm3, cudaFuncAttributeMaxDynamicSharedMemorySize, GEMM3_SMEM);
    cudaFuncSetAttribute(fa_kernel, cudaFuncAttributeMaxDynamicSharedMemorySize, FA_SMEM);

    float *qkv, *kvproj;
    cudaGetSymbolAddress((void**)&qkv,    g_qkv);
    cudaGetSymbolAddress((void**)&kvproj, g_kvproj);

    __nv_bfloat16 *xh, *xl, *wqkvh, *wqkvl, *wkvbh, *wkvbl, *woh, *wol;
    __nv_bfloat16 *kvnh, *kvnl, *Qh, *Ql, *Kh, *Kl, *Vth, *Vtl, *a2h, *a2l;
    cudaGetSymbolAddress((void**)&xh,    g_xh);    cudaGetSymbolAddress((void**)&xl,    g_xl);
    cudaGetSymbolAddress((void**)&wqkvh, g_wqkvh); cudaGetSymbolAddress((void**)&wqkvl, g_wqkvl);
    cudaGetSymbolAddress((void**)&wkvbh, g_wkvbh); cudaGetSymbolAddress((void**)&wkvbl, g_wkvbl);
    cudaGetSymbolAddress((void**)&woh,   g_woh);   cudaGetSymbolAddress((void**)&wol,   g_wol);
    cudaGetSymbolAddress((void**)&kvnh,  g_kvnh);  cudaGetSymbolAddress((void**)&kvnl,  g_kvnl);
    cudaGetSymbolAddress((void**)&Qh,    g_Qh);    cudaGetSymbolAddress((void**)&Ql,    g_Ql);
    cudaGetSymbolAddress((void**)&Kh,    g_Kh);    cudaGetSymbolAddress((void**)&Kl,    g_Kl);
    cudaGetSymbolAddress((void**)&Vth,   g_Vth);   cudaGetSymbolAddress((void**)&Vtl,   g_Vtl);
    cudaGetSymbolAddress((void**)&a2h,   g_a2h);   cudaGetSymbolAddress((void**)&a2l,   g_a2l);

    const int M = BB * SS;   // 4096

    // 0) pre-split inputs/weights to bf16 hi/lo. wq + wkv_a share one buffer
    //    (rows 0..3071 = wq, rows 3072..3647 = wkv_a) so steps 1+2 fuse.
    convert_kernel<<<1024, 256>>>(x,    xh,    xl,    (long long)BB * SS * DD / 4);
    convert_kernel<<<1024, 256>>>(wq,   wqkvh, wqkvl, (long long)(HH * QKD) * DD / 4);
    convert_kernel<<<1024, 256>>>(wkva, wqkvh + (size_t)(HH * QKD) * DD,
                                        wqkvl + (size_t)(HH * QKD) * DD,
                                        (long long)KV_A * DD / 4);
    convert_kernel<<<1024, 256>>>(wkvb, wkvbh, wkvbl, (long long)KV_PROJ * KV_RANK / 4);
    convert_kernel<<<1024, 256>>>(wo,   woh,   wol,   (long long)DD * DD / 4);

    // 1) qkv_raw = X @ [wq; wkv_a]^T   [4096,3648] K=2048  (merged)
    gemm3<<<dim3((QKV_N + 127) / 128, M / 128, 1), 256, GEMM3_SMEM>>>(
        xh, xl, wqkvh, wqkvl, qkv, M, QKV_N, DD, DD, DD, QKV_N, 0, 0, 0, 1.f);

    // 2) rmsnorm -> bf16 hi/lo
    rmsnorm_kernel<<<M, 256>>>(qkv, kvw, kvnh, kvnl);

    // 3) kv_proj = kvn @ wkv_b^T [4096,4096] K=512
    gemm3<<<dim3(KV_PROJ / 128, M / 128, 1), 256, GEMM3_SMEM>>>(
        kvnh, kvnl, wkvbh, wkvbl, kvproj, M, KV_PROJ, KV_RANK,
        KV_RANK, KV_RANK, KV_PROJ, 0, 0, 0, 1.f);

    // 4) RoPE + layout -> bf16 hi/lo Q/K/Vt
    prepare_kernel<<<M, 256>>>(qkv, kvproj, cosb, sinb, Qh, Ql, Kh, Kl, Vth, Vtl);

    // 5) fused attention (QK^T, online softmax, PV, regroup) -> a2h/a2l
    fa_kernel<<<dim3(SS / 128, BB * HH, 1), 256, FA_SMEM>>>(
        Qh, Ql, Kh, Kl, Vth, Vtl, a2h, a2l);

    // 6) out = attn2 @ wo^T      [4096,2048] K=2048
    gemm3<<<dim3(DD / 128, M / 128, 1), 256, GEMM3_SMEM>>>(
        a2h, a2l, woh, wol, out, M, DD, HH * VDIM,
        HH * VDIM, HH * VDIM, DD, 0, 0, 0, 1.f);
}

// round 14
// speedup vs baseline: 1.1139x; 1.0564x over previous
#include <cuda_runtime.h>
#include <cuda_bf16.h>
#include <cstdint>

// ---------------- problem constants ----------------
#define BB 2
#define SS 2048
#define DD 2048
#define HH 16
#define NOPE 128
#define ROPE 64
#define VDIM 128
#define QKD 192           // NOPE + ROPE
#define KV_RANK 512
#define KV_A (KV_RANK + ROPE)   // 576
#define KV_PROJ (HH * (NOPE + VDIM)) // 4096
#define QKV_N (HH * QKD + KV_A)      // 3648 (merged q + kv_a projection)
#define EPSV 1e-6f
#define ATT_SCALE 0.07216878364870323f  // 192^-0.5

// ---------------- fp32 scratch ----------------
__device__ __align__(16) float g_qkv   [(size_t)BB * SS * QKV_N];   // [B,S,3648]
__device__ __align__(16) float g_kvproj[(size_t)BB * SS * KV_PROJ];

// ---------------- bf16 hi/lo scratch ----------------
__device__ __align__(16) __nv_bfloat16 g_xh    [(size_t)BB * SS * DD];
__device__ __align__(16) __nv_bfloat16 g_xl    [(size_t)BB * SS * DD];
__device__ __align__(16) __nv_bfloat16 g_wqkvh [(size_t)QKV_N * DD];
__device__ __align__(16) __nv_bfloat16 g_wqkvl [(size_t)QKV_N * DD];
__device__ __align__(16) __nv_bfloat16 g_wkvbh [(size_t)KV_PROJ * KV_RANK];
__device__ __align__(16) __nv_bfloat16 g_wkvbl [(size_t)KV_PROJ * KV_RANK];
__device__ __align__(16) __nv_bfloat16 g_woh   [(size_t)DD * DD];
__device__ __align__(16) __nv_bfloat16 g_wol   [(size_t)DD * DD];
__device__ __align__(16) __nv_bfloat16 g_kvnh  [(size_t)BB * SS * KV_RANK];
__device__ __align__(16) __nv_bfloat16 g_kvnl  [(size_t)BB * SS * KV_RANK];
__device__ __align__(16) __nv_bfloat16 g_Qh    [(size_t)BB * HH * SS * QKD];
__device__ __align__(16) __nv_bfloat16 g_Ql    [(size_t)BB * HH * SS * QKD];
__device__ __align__(16) __nv_bfloat16 g_Kh    [(size_t)BB * HH * SS * QKD];
__device__ __align__(16) __nv_bfloat16 g_Kl    [(size_t)BB * HH * SS * QKD];
__device__ __align__(16) __nv_bfloat16 g_Vth   [(size_t)BB * HH * VDIM * SS];
__device__ __align__(16) __nv_bfloat16 g_Vtl   [(size_t)BB * HH * VDIM * SS];
__device__ __align__(16) __nv_bfloat16 g_a2h   [(size_t)BB * SS * HH * VDIM];
__device__ __align__(16) __nv_bfloat16 g_a2l   [(size_t)BB * SS * HH * VDIM];

// ---------------- helpers ----------------
__device__ __forceinline__ uint32_t smem_u32(const void* p) {
    uint32_t a;
    asm("{ .reg .u64 t; cvta.to.shared.u64 t, %1; cvt.u32.u64 %0, t; }" : "=r"(a) : "l"(p));
    return a;
}
__device__ __forceinline__ void split2(float x, __nv_bfloat16& h, __nv_bfloat16& l) {
    h = __float2bfloat16_rn(x);
    l = __float2bfloat16_rn(x - __bfloat162float(h));
}
__device__ __forceinline__ void packP(float a, float b, unsigned& hi, unsigned& lo) {
    __nv_bfloat16 ha = __float2bfloat16_rn(a);
    __nv_bfloat16 hb = __float2bfloat16_rn(b);
    __nv_bfloat16 la = __float2bfloat16_rn(a - __bfloat162float(ha));
    __nv_bfloat16 lb = __float2bfloat16_rn(b - __bfloat162float(hb));
    hi = ((unsigned)__bfloat16_as_ushort(hb) << 16) | __bfloat16_as_ushort(ha);
    lo = ((unsigned)__bfloat16_as_ushort(lb) << 16) | __bfloat16_as_ushort(la);
}
__device__ __forceinline__ void cp16(uint32_t d, const void* s) {
    asm volatile("cp.async.cg.shared.global [%0], [%1], 16;" :: "r"(d), "l"(s));
}
__device__ __forceinline__ void cp16z(uint32_t d, const void* s, unsigned bytes) {
    asm volatile("cp.async.cg.shared.global [%0], [%1], 16, %2;" :: "r"(d), "l"(s), "r"(bytes));
}

#define MMA16816(d, a, b) \
    asm volatile("mma.sync.aligned.m16n8k16.row.col.f32.bf16.bf16.f32 " \
                 "{%0,%1,%2,%3}, {%4,%5,%6,%7}, {%8,%9}, {%0,%1,%2,%3};" \
                 : "+f"((d)[0]), "+f"((d)[1]), "+f"((d)[2]), "+f"((d)[3]) \
                 : "r"((a)[0]), "r"((a)[1]), "r"((a)[2]), "r"((a)[3]), \
                   "r"((b)[0]), "r"((b)[1]))

#define LDMX4(r, ad) \
    asm volatile("ldmatrix.sync.aligned.m8n8.x4.shared.b16 {%0,%1,%2,%3}, [%4];" \
                 : "=r"((r)[0]), "=r"((r)[1]), "=r"((r)[2]), "=r"((r)[3]) : "r"(ad))
#define LDMX2(r, ad) \
    asm volatile("ldmatrix.sync.aligned.m8n8.x2.shared.b16 {%0,%1}, [%2];" \
                 : "=r"((r)[0]), "=r"((r)[1]) : "r"(ad))

// ======== bf16x3 GEMM: CTA 128x128, warp 64x32, 3-stage cp.async (R8) =========
#define MOFF 8192u
#define STG  32768u
#define GEMM3_SMEM 98304

__device__ __forceinline__ void g3_issue(
    uint32_t sb,
    const __nv_bfloat16* __restrict__ Ah, const __nv_bfloat16* __restrict__ Al,
    const __nv_bfloat16* __restrict__ Bh, const __nv_bfloat16* __restrict__ Bl,
    int bm, int bn, int N, int lda, int ldb, int k0, int tid)
{
#pragma unroll
    for (int half = 0; half < 2; half++) {
        int r  = (tid >> 2) + half * 64;
        int sg = tid & 3;
        int p  = sg ^ ((r >> 1) & 3);
        uint32_t d = sb + (uint32_t)(r * 64 + p * 16);
        long long ko = (long long)k0 + sg * 8;
        cp16(d,        Ah + (long long)(bm + r) * lda + ko);
        cp16(d + MOFF, Al + (long long)(bm + r) * lda + ko);
        int gn = bn + r;
        unsigned bytes = (gn < N) ? 16u : 0u;
        int gr = (gn < N) ? gn : 0;
        cp16z(d + 2 * MOFF, Bh + (long long)gr * ldb + ko, bytes);
        cp16z(d + 3 * MOFF, Bl + (long long)gr * ldb + ko, bytes);
    }
    asm volatile("cp.async.commit_group;" ::: "memory");
}

__global__ __launch_bounds__(256, 2) void gemm3(
    const __nv_bfloat16* __restrict__ Ah, const __nv_bfloat16* __restrict__ Al,
    const __nv_bfloat16* __restrict__ Bh, const __nv_bfloat16* __restrict__ Bl,
    float* __restrict__ C,
    int M, int N, int K, int lda, int ldb, int ldc,
    long long sA, long long sB, long long sC, float alpha)
{
    extern __shared__ char sm[];
    const int z = blockIdx.z;
    Ah += z * sA; Al += z * sA; Bh += z * sB; Bl += z * sB; C += z * sC;

    const int tid  = threadIdx.x;
    const int lane = tid & 31;
    const int wid  = tid >> 5;
    const int g    = lane >> 2;
    const int tig  = lane & 3;
    const int wm   = wid >> 2;
    const int wn   = wid & 3;
    const int bm = blockIdx.y * 128;
    const int bn = blockIdx.x * 128;
    const uint32_t smb = smem_u32(sm);

    float acc[4][4][4];
#pragma unroll
    for (int i = 0; i < 4; i++)
#pragma unroll
        for (int j = 0; j < 4; j++)
#pragma unroll
            for (int q = 0; q < 4; q++) acc[i][j][q] = 0.f;

    const int nc = K >> 5;

    g3_issue(smb,       Ah, Al, Bh, Bl, bm, bn, N, lda, ldb, 0,  tid);
    g3_issue(smb + STG, Ah, Al, Bh, Bl, bm, bn, N, lda, ldb, 32, tid);

    const int l15 = lane & 15;
    const int l7  = lane & 7;
    const uint32_t aSel = (uint32_t)(lane >> 4);
    const uint32_t bSel = (uint32_t)(l15 >> 3);
    const uint32_t swzA = (uint32_t)((l15 >> 1) & 3);
    const uint32_t swzB = (uint32_t)((l7 >> 1) & 3);
    const uint32_t aBase = smb + (uint32_t)((wm * 64 + l15) * 64);
    const uint32_t bBase = smb + 2u * MOFF + (uint32_t)((wn * 32 + l7) * 64);

    for (int c = 0; c < nc; c++) {
        asm volatile("cp.async.wait_group 1;" ::: "memory");
        __syncthreads();

        if (c + 2 < nc) {
            g3_issue(smb + (uint32_t)((c + 2) % 3) * STG,
                     Ah, Al, Bh, Bl, bm, bn, N, lda, ldb, (c + 2) << 5, tid);
        } else {
            asm volatile("cp.async.commit_group;" ::: "memory");
        }

        const uint32_t so = (uint32_t)(c % 3) * STG;
#pragma unroll
        for (int kk = 0; kk < 2; kk++) {
            const uint32_t cA = (uint32_t)(kk * 2) + aSel;
            const uint32_t cB = (uint32_t)(kk * 2) + bSel;
            unsigned bh[4][2], blr[4][2];
#pragma unroll
            for (int nf = 0; nf < 4; nf++) {
                uint32_t ad = bBase + so + (uint32_t)(nf * 512) + ((cB ^ swzB) << 4);
                LDMX2(bh[nf], ad);
                LDMX2(blr[nf], ad + MOFF);
            }
#pragma unroll
            for (int mf = 0; mf < 4; mf++) {
                uint32_t ad = aBase + so + (uint32_t)(mf * 1024) + ((cA ^ swzA) << 4);
                unsigned ah[4], al[4];
                LDMX4(ah, ad);
                LDMX4(al, ad + MOFF);
#pragma unroll
                for (int nf = 0; nf < 4; nf++) {
                    MMA16816(acc[mf][nf], ah, bh[nf]);
                    MMA16816(acc[mf][nf], ah, blr[nf]);
                    MMA16816(acc[mf][nf], al, bh[nf]);
                }
            }
        }
    }

#pragma unroll
    for (int mf = 0; mf < 4; mf++) {
#pragma unroll
        for (int nf = 0; nf < 4; nf++) {
            int row = bm + wm * 64 + mf * 16 + g;
            int col = bn + wn * 32 + nf * 8 + 2 * tig;
            if (col < N) {
                float* p0 = C + (long long)row * ldc + col;
                p0[0] = alpha * acc[mf][nf][0];
                p0[1] = alpha * acc[mf][nf][1];
                float* p1 = p0 + (long long)8 * ldc;
                p1[0] = alpha * acc[mf][nf][2];
                p1[1] = alpha * acc[mf][nf][3];
            }
        }
    }
}

// ================= fused flash attention (bf16x3, online softmax) =============
// R10 layout: grid (16 q-tiles, 32 bh), 256 thr, warp = 16 q-rows x 128 kv.
#define FA_KOFF 98304u
#define FA_QLO  49152u
#define FA_VOFF 147456u
#define FA_SMEM 212992

__device__ __forceinline__ void fa_issueK(
    uint32_t smb, int stage,
    const __nv_bfloat16* __restrict__ Khp, const __nv_bfloat16* __restrict__ Klp,
    int c, int tid)
{
#pragma unroll
    for (int it = 0; it < 2; it++) {
        int u = tid + (it << 8);
        int r = u >> 2, sg = u & 3;
        int p = sg ^ ((r >> 1) & 3);
        uint32_t d = smb + FA_KOFF + (uint32_t)(stage * 16384 + r * 64 + p * 16);
        long long off = (long long)r * QKD + c * 32 + sg * 8;
        cp16(d,         Khp + off);
        cp16(d + 8192u, Klp + off);
    }
    asm volatile("cp.async.commit_group;" ::: "memory");
}

__device__ __forceinline__ void fa_issueV(
    uint32_t smb,
    const __nv_bfloat16* __restrict__ Vhp, const __nv_bfloat16* __restrict__ Vlp,
    int j, int tid)
{
#pragma unroll
    for (int it = 0; it < 8; it++) {
        int u = tid + (it << 8);            // 0..2047
        int cb = u >> 9, v = u & 511;
        int r = v >> 2, sg = v & 3;
        int p = sg ^ ((r >> 1) & 3);
        uint32_t d = smb + FA_VOFF + (uint32_t)(cb * 16384 + r * 64 + p * 16);
        long long off = (long long)r * SS + j * 128 + cb * 32 + sg * 8;
        cp16(d,         Vhp + off);
        cp16(d + 8192u, Vlp + off);
    }
    asm volatile("cp.async.commit_group;" ::: "memory");
}

__global__ __launch_bounds__(256, 1) void fa_kernel(
    const __nv_bfloat16* __restrict__ Qh, const __nv_bfloat16* __restrict__ Ql,
    const __nv_bfloat16* __restrict__ Kh, const __nv_bfloat16* __restrict__ Kl,
    const __nv_bfloat16* __restrict__ Vth, const __nv_bfloat16* __restrict__ Vtl,
    __nv_bfloat16* __restrict__ a2h, __nv_bfloat16* __restrict__ a2l)
{
    extern __shared__ char sm[];
    const int tid  = threadIdx.x;
    const int lane = tid & 31;
    const int wid  = tid >> 5;
    const int g    = lane >> 2;
    const int tig  = lane & 3;
    const int qt   = blockIdx.x;
    const int bh   = blockIdx.y;
    const int b    = bh >> 4, h = bh & 15;
    const uint32_t smb = smem_u32(sm);

    const long long qkBase = (long long)bh * SS * QKD;
    const __nv_bfloat16* QhB = Qh + qkBase + (long long)qt * 128 * QKD;
    const __nv_bfloat16* QlB = Ql + qkBase + (long long)qt * 128 * QKD;
    const __nv_bfloat16* KhB = Kh + qkBase;
    const __nv_bfloat16* KlB = Kl + qkBase;
    const __nv_bfloat16* VhB = Vth + (long long)bh * VDIM * SS;
    const __nv_bfloat16* VlB = Vtl + (long long)bh * VDIM * SS;

    // ---- Q load (once): 6 d-chunks hi/lo ----
    {
#pragma unroll
        for (int c = 0; c < 6; c++) {
#pragma unroll
            for (int it = 0; it < 2; it++) {
                int u = tid + (it << 8);
                int r = u >> 2, sg = u & 3;
                int p = sg ^ ((r >> 1) & 3);
                uint32_t d = smb + (uint32_t)(c * 8192 + r * 64 + p * 16);
                long long off = (long long)r * QKD + c * 32 + sg * 8;
                cp16(d,          QhB + off);
                cp16(d + FA_QLO, QlB + off);
            }
        }
        asm volatile("cp.async.commit_group;" ::: "memory");
    }
    fa_issueK(smb, 0, KhB, KlB, 0, tid);
    fa_issueK(smb, 1, KhB, KlB, 1, tid);

    float sacc[16][4], oacc[16][4];
    float m0 = -1e30f, m1 = -1e30f, l0 = 0.f, l1 = 0.f;
#pragma unroll
    for (int nf = 0; nf < 16; nf++)
#pragma unroll
        for (int q = 0; q < 4; q++) oacc[nf][q] = 0.f;

    const int l15 = lane & 15;
    const int l7  = lane & 7;
    const uint32_t aSel = (uint32_t)(lane >> 4);
    const uint32_t bSel = (uint32_t)(l15 >> 3);
    const uint32_t swzA = (uint32_t)((l15 >> 1) & 3);
    const uint32_t swzB = (uint32_t)((l7 >> 1) & 3);
    const uint32_t aRow = smb + (uint32_t)((wid * 16 + l15) * 64);
    const uint32_t kRow = smb + FA_KOFF + (uint32_t)(l7 * 64);
    const uint32_t vRow = smb + FA_VOFF + (uint32_t)(l7 * 64);

    for (int j = 0; j < 16; j++) {
        __syncthreads();                       // PV(j-1) readers done before V overwrite
        fa_issueV(smb, VhB, VlB, j, tid);

#pragma unroll
        for (int nf = 0; nf < 16; nf++) {
            sacc[nf][0] = 0.f; sacc[nf][1] = 0.f; sacc[nf][2] = 0.f; sacc[nf][3] = 0.f;
        }

        for (int c = 0; c < 6; c++) {
            const int gc = j * 6 + c;
            if (c < 2) asm volatile("cp.async.wait_group 2;" ::: "memory");
            else       asm volatile("cp.async.wait_group 1;" ::: "memory");
            __syncthreads();

            const int gcI = gc + 2;
            if (gcI < 96) {
                const int jI = gcI / 6, cI = gcI % 6;
                fa_issueK(smb, gcI % 3,
                          KhB + (long long)jI * 128 * QKD,
                          KlB + (long long)jI * 128 * QKD, cI, tid);
            } else {
                asm volatile("cp.async.commit_group;" ::: "memory");
            }

            const uint32_t aB = aRow + (uint32_t)(c * 8192);
            const uint32_t kB = kRow + (uint32_t)((gc % 3) * 16384);
#pragma unroll
            for (int kk = 0; kk < 2; kk++) {
                const uint32_t cA = (uint32_t)(kk * 2) + aSel;
                const uint32_t cB = (uint32_t)(kk * 2) + bSel;
                uint32_t aAd = aB + ((cA ^ swzA) << 4);
                unsigned ah[4], al[4];
                LDMX4(ah, aAd);
                LDMX4(al, aAd + FA_QLO);
#pragma unroll
                for (int nf = 0; nf < 16; nf++) {
                    uint32_t bAd = kB + (uint32_t)(nf * 512) + ((cB ^ swzB) << 4);
                    unsigned kh2[2], kl2[2];
                    LDMX2(kh2, bAd);
                    LDMX2(kl2, bAd + 8192u);
                    MMA16816(sacc[nf], ah, kh2);
                    MMA16816(sacc[nf], ah, kl2);
                    MMA16816(sacc[nf], al, kh2);
                }
            }
        }

        // ---- online softmax (warp-local; rows g and g+8) ----
        float mx0 = -1e30f, mx1 = -1e30f;
#pragma unroll
        for (int nf = 0; nf < 16; nf++) {
            mx0 = fmaxf(mx0, fmaxf(sacc[nf][0], sacc[nf][1]));
            mx1 = fmaxf(mx1, fmaxf(sacc[nf][2], sacc[nf][3]));
        }
        mx0 = fmaxf(mx0, __shfl_xor_sync(0xffffffffu, mx0, 1));
        mx0 = fmaxf(mx0, __shfl_xor_sync(0xffffffffu, mx0, 2));
        mx1 = fmaxf(mx1, __shfl_xor_sync(0xffffffffu, mx1, 1));
        mx1 = fmaxf(mx1, __shfl_xor_sync(0xffffffffu, mx1, 2));
        const float mn0 = fmaxf(m0, mx0 * ATT_SCALE);
        const float mn1 = fmaxf(m1, mx1 * ATT_SCALE);
        const float cf0 = __expf(m0 - mn0);
        const float cf1 = __expf(m1 - mn1);
        float s0 = 0.f, s1 = 0.f;
#pragma unroll
        for (int nf = 0; nf < 16; nf++) {
            float p0 = __expf(sacc[nf][0] * ATT_SCALE - mn0);
            float p1 = __expf(sacc[nf][1] * ATT_SCALE - mn0);
            float p2 = __expf(sacc[nf][2] * ATT_SCALE - mn1);
            float p3 = __expf(sacc[nf][3] * ATT_SCALE - mn1);
            sacc[nf][0] = p0; sacc[nf][1] = p1; sacc[nf][2] = p2; sacc[nf][3] = p3;
            s0 += p0 + p1; s1 += p2 + p3;
        }
        s0 += __shfl_xor_sync(0xffffffffu, s0, 1);
        s0 += __shfl_xor_sync(0xffffffffu, s0, 2);
        s1 += __shfl_xor_sync(0xffffffffu, s1, 1);
        s1 += __shfl_xor_sync(0xffffffffu, s1, 2);
        l0 = l0 * cf0 + s0; l1 = l1 * cf1 + s1;
        m0 = mn0; m1 = mn1;
#pragma unroll
        for (int nf = 0; nf < 16; nf++) {
            oacc[nf][0] *= cf0; oacc[nf][1] *= cf0;
            oacc[nf][2] *= cf1; oacc[nf][3] *= cf1;
        }

        // ---- PV: P from registers (acc->A frag remap), V from smem ----
#pragma unroll
        for (int kc = 0; kc < 8; kc++) {
            unsigned ah[4], al[4];
            packP(sacc[2 * kc][0],     sacc[2 * kc][1],     ah[0], al[0]);
            packP(sacc[2 * kc][2],     sacc[2 * kc][3],     ah[1], al[1]);
            packP(sacc[2 * kc + 1][0], sacc[2 * kc + 1][1], ah[2], al[2]);
            packP(sacc[2 * kc + 1][2], sacc[2 * kc + 1][3], ah[3], al[3]);
            const uint32_t vB = vRow + (uint32_t)((kc >> 1) * 16384);
            const uint32_t cV = (uint32_t)((kc & 1) * 2) + bSel;
#pragma unroll
            for (int nf = 0; nf < 16; nf++) {
                uint32_t bAd = vB + (uint32_t)(nf * 512) + ((cV ^ swzB) << 4);
                unsigned vh2[2], vl2[2];
                LDMX2(vh2, bAd);
                LDMX2(vl2, bAd + 8192u);
                MMA16816(oacc[nf], ah, vh2);
                MMA16816(oacc[nf], ah, vl2);
                MMA16816(oacc[nf], al, vh2);
            }
        }
    }

    // ---- epilogue: normalize, split hi/lo, write a2 (regroup fused) ----
    const float li0 = 1.f / l0, li1 = 1.f / l1;
    const int srow = qt * 128 + wid * 16 + g;
    const long long base0 = ((long long)(b * SS) + srow) * (HH * VDIM) + h * VDIM;
    const long long base1 = base0 + 8ll * (HH * VDIM);
#pragma unroll
    for (int nf = 0; nf < 16; nf++) {
        const int d = nf * 8 + 2 * tig;
        unsigned hh, ll;
        packP(oacc[nf][0] * li0, oacc[nf][1] * li0, hh, ll);
        *(unsigned*)(a2h + base0 + d) = hh;
        *(unsigned*)(a2l + base0 + d) = ll;
        packP(oacc[nf][2] * li1, oacc[nf][3] * li1, hh, ll);
        *(unsigned*)(a2h + base1 + d) = hh;
        *(unsigned*)(a2l + base1 + d) = ll;
    }
}

// ---------------- fp32 -> bf16 hi/lo converter ----------------
__global__ void convert_kernel(const float* __restrict__ in,
                               __nv_bfloat16* __restrict__ hp,
                               __nv_bfloat16* __restrict__ lp, long long n4)
{
    for (long long i = (long long)blockIdx.x * 256 + threadIdx.x; i < n4;
         i += (long long)gridDim.x * 256) {
        float4 v = ((const float4*)in)[i];
        __nv_bfloat16 h0, h1, h2, h3, l0, l1, l2, l3;
        split2(v.x, h0, l0); split2(v.y, h1, l1);
        split2(v.z, h2, l2); split2(v.w, h3, l3);
        uint2 hh, ll;
        hh.x = ((unsigned)__bfloat16_as_ushort(h1) << 16) | __bfloat16_as_ushort(h0);
        hh.y = ((unsigned)__bfloat16_as_ushort(h3) << 16) | __bfloat16_as_ushort(h2);
        ll.x = ((unsigned)__bfloat16_as_ushort(l1) << 16) | __bfloat16_as_ushort(l0);
        ll.y = ((unsigned)__bfloat16_as_ushort(l3) << 16) | __bfloat16_as_ushort(l2);
        ((uint2*)hp)[i] = hh;
        ((uint2*)lp)[i] = ll;
    }
}

// ---------------- rmsnorm over KV_RANK (reads merged qkv buffer) --------------
__global__ void rmsnorm_kernel(const float* __restrict__ qkv,
                               const float* __restrict__ w,
                               __nv_bfloat16* __restrict__ oh,
                               __nv_bfloat16* __restrict__ ol)
{
    const int row = blockIdx.x;
    const float* x = qkv + (long long)row * QKV_N + HH * QKD;   // kv_all[0:512]
    __shared__ float red[256];
    float ss = 0.f;
    for (int i = threadIdx.x; i < KV_RANK; i += 256) { float v = x[i]; ss += v * v; }
    red[threadIdx.x] = ss; __syncthreads();
    for (int st = 128; st > 0; st >>= 1) {
        if (threadIdx.x < st) red[threadIdx.x] += red[threadIdx.x + st];
        __syncthreads();
    }
    float scale = rsqrtf(red[0] / (float)KV_RANK + EPSV);
    for (int i = threadIdx.x; i < KV_RANK; i += 256) {
        float v = x[i] * scale * w[i];
        __nv_bfloat16 h, l; split2(v, h, l);
        oh[(long long)row * KV_RANK + i] = h;
        ol[(long long)row * KV_RANK + i] = l;
    }
}

// ---------------- RoPE + layout prep (Q/K only; V handled by vtrans) ----------
__global__ void prepare_kernel(const float* __restrict__ qkv,
                               const float* __restrict__ kvproj,
                               const float* __restrict__ cosb,
                               const float* __restrict__ sinb,
                               __nv_bfloat16* __restrict__ Qh, __nv_bfloat16* __restrict__ Ql,
                               __nv_bfloat16* __restrict__ Kh, __nv_bfloat16* __restrict__ Kl)
{
    const int bs = blockIdx.x;
    const int b = bs / SS, s = bs % SS;
    const float* cs = cosb + (long long)s * ROPE;
    const float* sn = sinb + (long long)s * ROPE;

    __shared__ float kpe[ROPE];
    if (threadIdx.x < ROPE) {
        int j = threadIdx.x;
        const float* kp = qkv + (long long)bs * QKV_N + HH * QKD + KV_RANK;
        float x  = kp[j];
        float xr = (j < 32) ? -kp[j + 32] : kp[j - 32];
        kpe[j] = x * cs[j] + xr * sn[j];
    }
    __syncthreads();

    const float* qrow = qkv + (long long)bs * QKV_N;
    const float* prow = kvproj + (long long)bs * KV_PROJ;

    for (int idx = threadIdx.x; idx < HH * QKD; idx += blockDim.x) {
        int h = idx / QKD, d = idx % QKD;
        long long off = (((long long)(b * HH + h)) * SS + s) * QKD + d;
        float qv;
        if (d < NOPE) {
            qv = qrow[h * QKD + d];
        } else {
            int j = d - NOPE;
            float x  = qrow[h * QKD + NOPE + j];
            float xr = (j < 32) ? -qrow[h * QKD + NOPE + j + 32]
                                :  qrow[h * QKD + NOPE + j - 32];
            qv = x * cs[j] + xr * sn[j];
        }
        __nv_bfloat16 hh, ll;
        split2(qv, hh, ll); Qh[off] = hh; Ql[off] = ll;
        float kv = (d < NOPE) ? prow[h * (NOPE + VDIM) + d] : kpe[d - NOPE];
        split2(kv, hh, ll); Kh[off] = hh; Kl[off] = ll;
    }
}

// ------- V transpose: kvproj [b,s][h*256+128+d] -> Vt [bh][d][s] (coalesced) --
// Grid (bh=32, st=SS/64, dt=VDIM/64), 256 threads, smem 64x65 fp32 tile.
__global__ void vtrans_kernel(const float* __restrict__ kvproj,
                              __nv_bfloat16* __restrict__ Vth,
                              __nv_bfloat16* __restrict__ Vtl)
{
    __shared__ float tile[64][65];
    const int bh = blockIdx.x;
    const int st = blockIdx.y;     // s-tile of 64
    const int dt = blockIdx.z;     // d-tile of 64
    const int b = bh >> 4, h = bh & 15;
    const int tid = threadIdx.x;

    // load 64 s-rows x 64 d (coalesced 256B rows)
    const long long srcBase = ((long long)(b * SS) + st * 64) * KV_PROJ
                            + h * (NOPE + VDIM) + NOPE + dt * 64;
#pragma unroll
    for (int it = 0; it < 16; it++) {
        int idx = tid + it * 256;          // 0..4095
        int r = idx >> 6, dcol = idx & 63;
        tile[r][dcol] = kvproj[srcBase + (long long)r * KV_PROJ + dcol];
    }
    __syncthreads();

    // write 64 d-rows x 64 s (coalesced 128B rows), split hi/lo
    const long long dstBase = ((long long)(bh * VDIM) + dt * 64) * SS + st * 64;
#pragma unroll
    for (int it = 0; it < 16; it++) {
        int idx = tid + it * 256;
        int dr = idx >> 6, sc = idx & 63;
        float v = tile[sc][dr];
        __nv_bfloat16 hh, ll; split2(v, hh, ll);
        long long o = dstBase + (long long)dr * SS + sc;
        Vth[o] = hh; Vtl[o] = ll;
    }
}

// ---------------- launch ----------------
extern "C" void kernel_launch(void* const* d_in, const int* in_sizes, int n_in,
                              void* d_out, int out_size)
{
    const float* x    = (const float*)d_in[0];
    const float* cosb = (const float*)d_in[1];
    const float* sinb = (const float*)d_in[2];
    const float* wq   = (const float*)d_in[3];
    const float* wkva = (const float*)d_in[4];
    const float* kvw  = (const float*)d_in[5];
    const float* wkvb = (const float*)d_in[6];
    const float* wo   = (const float*)d_in[7];
    float* out = (float*)d_out;

    cudaFuncSetAttribute(gemm3, cudaFuncAttributeMaxDynamicSharedMemorySize, GEMM3_SMEM);
    cudaFuncSetAttribute(fa_kernel, cudaFuncAttributeMaxDynamicSharedMemorySize, FA_SMEM);

    float *qkv, *kvproj;
    cudaGetSymbolAddress((void**)&qkv,    g_qkv);
    cudaGetSymbolAddress((void**)&kvproj, g_kvproj);

    __nv_bfloat16 *xh, *xl, *wqkvh, *wqkvl, *wkvbh, *wkvbl, *woh, *wol;
    __nv_bfloat16 *kvnh, *kvnl, *Qh, *Ql, *Kh, *Kl, *Vth, *Vtl, *a2h, *a2l;
    cudaGetSymbolAddress((void**)&xh,    g_xh);    cudaGetSymbolAddress((void**)&xl,    g_xl);
    cudaGetSymbolAddress((void**)&wqkvh, g_wqkvh); cudaGetSymbolAddress((void**)&wqkvl, g_wqkvl);
    cudaGetSymbolAddress((void**)&wkvbh, g_wkvbh); cudaGetSymbolAddress((void**)&wkvbl, g_wkvbl);
    cudaGetSymbolAddress((void**)&woh,   g_woh);   cudaGetSymbolAddress((void**)&wol,   g_wol);
    cudaGetSymbolAddress((void**)&kvnh,  g_kvnh);  cudaGetSymbolAddress((void**)&kvnl,  g_kvnl);
    cudaGetSymbolAddress((void**)&Qh,    g_Qh);    cudaGetSymbolAddress((void**)&Ql,    g_Ql);
    cudaGetSymbolAddress((void**)&Kh,    g_Kh);    cudaGetSymbolAddress((void**)&Kl,    g_Kl);
    cudaGetSymbolAddress((void**)&Vth,   g_Vth);   cudaGetSymbolAddress((void**)&Vtl,   g_Vtl);
    cudaGetSymbolAddress((void**)&a2h,   g_a2h);   cudaGetSymbolAddress((void**)&a2l,   g_a2l);

    const int M = BB * SS;   // 4096

    // 0) pre-split inputs/weights to bf16 hi/lo (wq+wkv_a share one buffer)
    convert_kernel<<<1024, 256>>>(x,    xh,    xl,    (long long)BB * SS * DD / 4);
    convert_kernel<<<1024, 256>>>(wq,   wqkvh, wqkvl, (long long)(HH * QKD) * DD / 4);
    convert_kernel<<<1024, 256>>>(wkva, wqkvh + (size_t)(HH * QKD) * DD,
                                        wqkvl + (size_t)(HH * QKD) * DD,
                                        (long long)KV_A * DD / 4);
    convert_kernel<<<1024, 256>>>(wkvb, wkvbh, wkvbl, (long long)KV_PROJ * KV_RANK / 4);
    convert_kernel<<<1024, 256>>>(wo,   woh,   wol,   (long long)DD * DD / 4);

    // 1) qkv_raw = X @ [wq; wkv_a]^T   [4096,3648] K=2048  (merged)
    gemm3<<<dim3((QKV_N + 127) / 128, M / 128, 1), 256, GEMM3_SMEM>>>(
        xh, xl, wqkvh, wqkvl, qkv, M, QKV_N, DD, DD, DD, QKV_N, 0, 0, 0, 1.f);

    // 2) rmsnorm -> bf16 hi/lo
    rmsnorm_kernel<<<M, 256>>>(qkv, kvw, kvnh, kvnl);

    // 3) kv_proj = kvn @ wkv_b^T [4096,4096] K=512
    gemm3<<<dim3(KV_PROJ / 128, M / 128, 1), 256, GEMM3_SMEM>>>(
        kvnh, kvnl, wkvbh, wkvbl, kvproj, M, KV_PROJ, KV_RANK,
        KV_RANK, KV_RANK, KV_PROJ, 0, 0, 0, 1.f);

    // 4a) V transpose (coalesced both sides) -> Vt bf16 hi/lo
    vtrans_kernel<<<dim3(BB * HH, SS / 64, VDIM / 64), 256>>>(kvproj, Vth, Vtl);

    // 4b) RoPE + layout for Q/K -> bf16 hi/lo
    prepare_kernel<<<M, 256>>>(qkv, kvproj, cosb, sinb, Qh, Ql, Kh, Kl);

    // 5) fused attention (QK^T, online softmax, PV, regroup) -> a2h/a2l
    fa_kernel<<<dim3(SS / 128, BB * HH, 1), 256, FA_SMEM>>>(
        Qh, Ql, Kh, Kl, Vth, Vtl, a2h, a2l);

    // 6) out = attn2 @ wo^T      [4096,2048] K=2048
    gemm3<<<dim3(DD / 128, M / 128, 1), 256, GEMM3_SMEM>>>(
        a2h, a2l, woh, wol, out, M, DD, HH * VDIM,
        HH * VDIM, HH * VDIM, DD, 0, 0, 0, 1.f);
}